// round 1
// baseline (speedup 1.0000x reference)
#include <cuda_runtime.h>
#include <math.h>

typedef unsigned long long u64;

// ---------------- scratch (device globals; no allocs allowed) ----------------
__device__ float g_weT[512 * 32];        // we transposed [e][b]
__device__ float g_se[1024 * 512];       // se [(t*32+b)][e]
__device__ float g_bsum[4096];           // bih + bhh
__device__ float g_gx[1024 * 4096];      // se @ Wih.T + bsum   [(t*32+b)][4H]
__device__ float g_hT[1024 * 32];        // h  [j][b]
__device__ float g_cT[1024 * 32];        // c  [j][b]
__device__ float g_h1T[1024 * 32];       // post-LSTM h [j][b]
__device__ float g_zcT[1024 * 32];       // we-part of z preact [j][b]
__device__ float g_rcT[512 * 32];        // we-part of r preact [e][b]
__device__ float g_zT[1024 * 32];        // z [j][b]
__device__ float g_t1T[1024 * 32];       // h1 @ Wh_h.T [j][b]
__device__ float g_rwT[512 * 32];        // r * we [e][b]
__device__ float g_hs[1024 * 1024];      // hs [(t*32+b)][j]  (GEMM A)

__device__ __forceinline__ float sigf(float x) { return 1.f / (1.f + expf(-x)); }

__device__ __forceinline__ u64 fma2(u64 a, u64 b, u64 c) {
    u64 d;
    asm("fma.rn.f32x2 %0, %1, %2, %3;" : "=l"(d) : "l"(a), "l"(b), "l"(c));
    return d;
}

// ---------------- gather: we (transposed), se, bias sum ----------------
__global__ void k_gather(const int* __restrict__ word, const int* __restrict__ seq,
                         const float* __restrict__ emb,
                         const float* __restrict__ bih, const float* __restrict__ bhh)
{
    int idx = blockIdx.x * blockDim.x + threadIdx.x;
    if (idx < 1024 * 512) {
        int m = idx >> 9, e = idx & 511;
        g_se[idx] = emb[(size_t)seq[m] * 512 + e];
    }
    if (idx < 512 * 32) {
        int e = idx >> 5, b = idx & 31;
        g_weT[idx] = emb[(size_t)word[b] * 512 + e];
    }
    if (idx < 4096) g_bsum[idx] = bih[idx] + bhh[idx];
}

// ---------------- prep: h0 (-> h,c), zc, rc ; one warp per output row ----------------
__global__ void k_prep(const float* __restrict__ Wl, const float* __restrict__ bl,
                       const float* __restrict__ Wz, const float* __restrict__ bz,
                       const float* __restrict__ Wr, const float* __restrict__ br)
{
    int w = (blockIdx.x * blockDim.x + threadIdx.x) >> 5;   // 0..2559
    int lane = threadIdx.x & 31;                            // = b
    const float* wr;
    float bias;
    if (w < 1024)      { wr = Wl + (size_t)w * 512;            bias = bl[w]; }
    else if (w < 2048) { wr = Wz + (size_t)(w - 1024) * 1536;  bias = bz[w - 1024]; }
    else               { wr = Wr + (size_t)(w - 2048) * 1536;  bias = br[w - 2048]; }
    float acc = 0.f;
#pragma unroll 4
    for (int e = 0; e < 512; e += 4) {
        float4 wv = *(const float4*)(wr + e);
        acc += g_weT[(e + 0) * 32 + lane] * wv.x + g_weT[(e + 1) * 32 + lane] * wv.y
             + g_weT[(e + 2) * 32 + lane] * wv.z + g_weT[(e + 3) * 32 + lane] * wv.w;
    }
    acc += bias;
    if (w < 1024)      { g_hT[w * 32 + lane] = acc; g_cT[w * 32 + lane] = acc; }
    else if (w < 2048) { g_zcT[(w - 1024) * 32 + lane] = acc; }
    else               { g_rcT[(w - 2048) * 32 + lane] = acc; }
}

// ---------------- tiled f32x2 GEMM: C[M,N] = A[M,K] * B[N,K]^T + bias[N] ----------------
// BM=BN=128, BK=16, 256 threads, 8x8 per thread (n in f32x2 pairs, A duplicated in smem)
__global__ void __launch_bounds__(256) gemm_f32x2(
    const float* __restrict__ A, const float* __restrict__ B,
    const float* __restrict__ bias, float* __restrict__ C,
    int M, int N, int K)
{
    const int BK = 16;
    __shared__ __align__(16) float As[16][256];  // duplicated pairs: As[k][2m],[2m+1]
    __shared__ __align__(16) float Bs[16][128];

    const int tid = threadIdx.x;
    const int mBase = blockIdx.x * 128;
    const int nBase = blockIdx.y * 128;

    const int lm  = tid >> 2;        // 0..63 (row within tile; also +64)
    const int lk4 = (tid & 3) * 4;   // 0,4,8,12

    const float* Aptr = A + (size_t)(mBase + lm) * K + lk4;
    const float* Bptr = B + (size_t)(nBase + lm) * K + lk4;

    const int ty = tid >> 4;     // 0..15
    const int tx = tid & 15;     // 0..15
    const int m0 = ty * 8;
    const int n0 = tx * 8;

    u64 acc[8][4];
#pragma unroll
    for (int i = 0; i < 8; i++)
#pragma unroll
        for (int p = 0; p < 4; p++) acc[i][p] = 0ull;

    // load tile 0
    float4 pa0 = *(const float4*)(Aptr);
    float4 pa1 = *(const float4*)(Aptr + (size_t)64 * K);
    float4 pb0 = *(const float4*)(Bptr);
    float4 pb1 = *(const float4*)(Bptr + (size_t)64 * K);

#define STORE_A(v, m)  { As[lk4+0][2*(m)] = (v).x; As[lk4+0][2*(m)+1] = (v).x; \
                         As[lk4+1][2*(m)] = (v).y; As[lk4+1][2*(m)+1] = (v).y; \
                         As[lk4+2][2*(m)] = (v).z; As[lk4+2][2*(m)+1] = (v).z; \
                         As[lk4+3][2*(m)] = (v).w; As[lk4+3][2*(m)+1] = (v).w; }
#define STORE_B(v, n)  { Bs[lk4+0][(n)] = (v).x; Bs[lk4+1][(n)] = (v).y; \
                         Bs[lk4+2][(n)] = (v).z; Bs[lk4+3][(n)] = (v).w; }

    STORE_A(pa0, lm); STORE_A(pa1, lm + 64);
    STORE_B(pb0, lm); STORE_B(pb1, lm + 64);
    __syncthreads();

    int ktile = 0;
    while (true) {
        ktile += BK;
        bool more = (ktile < K);
        if (more) {
            pa0 = *(const float4*)(Aptr + ktile);
            pa1 = *(const float4*)(Aptr + (size_t)64 * K + ktile);
            pb0 = *(const float4*)(Bptr + ktile);
            pb1 = *(const float4*)(Bptr + (size_t)64 * K + ktile);
        }
#pragma unroll
        for (int k = 0; k < BK; k++) {
            u64 a[8], b[4];
            const u64* ap = reinterpret_cast<const u64*>(&As[k][2 * m0]);
#pragma unroll
            for (int i = 0; i < 8; i++) a[i] = ap[i];
            const u64* bp = reinterpret_cast<const u64*>(&Bs[k][n0]);
#pragma unroll
            for (int p = 0; p < 4; p++) b[p] = bp[p];
#pragma unroll
            for (int i = 0; i < 8; i++)
#pragma unroll
                for (int p = 0; p < 4; p++) acc[i][p] = fma2(a[i], b[p], acc[i][p]);
        }
        if (!more) break;
        __syncthreads();
        STORE_A(pa0, lm); STORE_A(pa1, lm + 64);
        STORE_B(pb0, lm); STORE_B(pb1, lm + 64);
        __syncthreads();
    }

#pragma unroll
    for (int i = 0; i < 8; i++) {
        float* crow = C + (size_t)(mBase + m0 + i) * N + nBase + n0;
#pragma unroll
        for (int p = 0; p < 4; p++) {
            float2 v = *reinterpret_cast<float2*>(&acc[i][p]);
            if (bias) {
                v.x += bias[nBase + n0 + 2 * p];
                v.y += bias[nBase + n0 + 2 * p + 1];
            }
            *reinterpret_cast<float2*>(crow + 2 * p) = v;
        }
    }
#undef STORE_A
#undef STORE_B
}

// ---------------- per-step: gates GEMV (4 rows/warp) + LSTM pointwise ----------------
__global__ void k_gates(const float* __restrict__ Whh, int t)
{
    int j = (blockIdx.x * blockDim.x + threadIdx.x) >> 5;   // 0..1023
    int lane = threadIdx.x & 31;                            // = b
    const float* Wi  = Whh + (size_t)j * 1024;
    const float* Wf  = Wi + (size_t)1024 * 1024;
    const float* Wg  = Wf + (size_t)1024 * 1024;
    const float* Wo_ = Wg + (size_t)1024 * 1024;
    float ai = 0.f, af = 0.f, ag = 0.f, ao = 0.f;
#pragma unroll 4
    for (int k = 0; k < 1024; k += 4) {
        float h0v = g_hT[(k + 0) * 32 + lane];
        float h1v = g_hT[(k + 1) * 32 + lane];
        float h2v = g_hT[(k + 2) * 32 + lane];
        float h3v = g_hT[(k + 3) * 32 + lane];
        float4 wi = *(const float4*)(Wi + k);
        float4 wf = *(const float4*)(Wf + k);
        float4 wg = *(const float4*)(Wg + k);
        float4 wo = *(const float4*)(Wo_ + k);
        ai += h0v * wi.x + h1v * wi.y + h2v * wi.z + h3v * wi.w;
        af += h0v * wf.x + h1v * wf.y + h2v * wf.z + h3v * wf.w;
        ag += h0v * wg.x + h1v * wg.y + h2v * wg.z + h3v * wg.w;
        ao += h0v * wo.x + h1v * wo.y + h2v * wo.z + h3v * wo.w;
    }
    const float* gx = g_gx + (size_t)(t * 32 + lane) * 4096 + j;
    float gi = gx[0] + ai;
    float gf = gx[1024] + af;
    float gg = gx[2048] + ag;
    float go = gx[3072] + ao;
    float co = g_cT[j * 32 + lane];
    float cn = sigf(gf) * co + sigf(gi) * tanhf(gg);
    g_cT[j * 32 + lane] = cn;
    g_h1T[j * 32 + lane] = sigf(go) * tanhf(cn);
}

// ---------------- per-step: z, t1 = h1@Wh_h.T, r*we ----------------
__global__ void k_zrt(const float* __restrict__ Wz, const float* __restrict__ Wh,
                      const float* __restrict__ Wr)
{
    int w = (blockIdx.x * blockDim.x + threadIdx.x) >> 5;   // 0..2559
    int lane = threadIdx.x & 31;
    const float* wr;
    if (w < 1024)      wr = Wz + (size_t)w * 1536 + 512;
    else if (w < 2048) wr = Wh + (size_t)(w - 1024) * 1536 + 512;
    else               wr = Wr + (size_t)(w - 2048) * 1536 + 512;
    float acc = 0.f;
#pragma unroll 8
    for (int k = 0; k < 1024; k += 4) {
        float4 wv = *(const float4*)(wr + k);
        acc += g_h1T[(k + 0) * 32 + lane] * wv.x + g_h1T[(k + 1) * 32 + lane] * wv.y
             + g_h1T[(k + 2) * 32 + lane] * wv.z + g_h1T[(k + 3) * 32 + lane] * wv.w;
    }
    if (w < 1024) {
        g_zT[w * 32 + lane] = sigf(g_zcT[w * 32 + lane] + acc);
    } else if (w < 2048) {
        g_t1T[(w - 1024) * 32 + lane] = acc;
    } else {
        int e = w - 2048;
        float r = sigf(g_rcT[e * 32 + lane] + acc);
        g_rwT[e * 32 + lane] = r * g_weT[e * 32 + lane];
    }
}

// ---------------- per-step: hh, final h update, write hs ----------------
__global__ void k_hh(const float* __restrict__ Wh, const float* __restrict__ bh, int t)
{
    int j = (blockIdx.x * blockDim.x + threadIdx.x) >> 5;   // 0..1023
    int lane = threadIdx.x & 31;
    const float* wr = Wh + (size_t)j * 1536;
    float acc = 0.f;
#pragma unroll 8
    for (int e = 0; e < 512; e += 4) {
        float4 wv = *(const float4*)(wr + e);
        acc += g_rwT[(e + 0) * 32 + lane] * wv.x + g_rwT[(e + 1) * 32 + lane] * wv.y
             + g_rwT[(e + 2) * 32 + lane] * wv.z + g_rwT[(e + 3) * 32 + lane] * wv.w;
    }
    float hh = tanhf(g_t1T[j * 32 + lane] + acc + bh[j]);
    float z  = g_zT[j * 32 + lane];
    float h1 = g_h1T[j * 32 + lane];
    float hn = (1.f - z) * h1 + z * hh;
    g_hT[j * 32 + lane] = hn;
    g_hs[(size_t)(t * 32 + lane) * 1024 + j] = hn;
}

// ---------------- tail: hf, cf into output ----------------
__global__ void k_tail(float* __restrict__ out)
{
    int idx = blockIdx.x * blockDim.x + threadIdx.x;   // < 32768
    int b = idx >> 10, j = idx & 1023;
    out[32768000 + idx]         = g_hT[j * 32 + b];
    out[32768000 + 32768 + idx] = g_cT[j * 32 + b];
}

// ---------------- launch ----------------
extern "C" void kernel_launch(void* const* d_in, const int* in_sizes, int n_in,
                              void* d_out, int out_size)
{
    const int*   word = (const int*)d_in[0];
    const int*   seq  = (const int*)d_in[1];
    const float* emb  = (const float*)d_in[2];
    const float* Wl   = (const float*)d_in[3];
    const float* bl   = (const float*)d_in[4];
    const float* Wih  = (const float*)d_in[5];
    const float* Whh  = (const float*)d_in[6];
    const float* bih  = (const float*)d_in[7];
    const float* bhh  = (const float*)d_in[8];
    const float* Wz   = (const float*)d_in[9];
    const float* bz   = (const float*)d_in[10];
    const float* Wr   = (const float*)d_in[11];
    const float* br   = (const float*)d_in[12];
    const float* Wh   = (const float*)d_in[13];
    const float* bh   = (const float*)d_in[14];
    const float* Wo   = (const float*)d_in[15];
    const float* bo   = (const float*)d_in[16];
    float* out = (float*)d_out;

    void *p_se, *p_gx, *p_bsum, *p_hs;
    cudaGetSymbolAddress(&p_se, g_se);
    cudaGetSymbolAddress(&p_gx, g_gx);
    cudaGetSymbolAddress(&p_bsum, g_bsum);
    cudaGetSymbolAddress(&p_hs, g_hs);

    k_gather<<<2048, 256>>>(word, seq, emb, bih, bhh);
    k_prep<<<320, 256>>>(Wl, bl, Wz, bz, Wr, br);

    // gx = se @ Wih.T + (bih+bhh):  M=1024, N=4096, K=512
    gemm_f32x2<<<dim3(8, 32), 256>>>((const float*)p_se, Wih, (const float*)p_bsum,
                                     (float*)p_gx, 1024, 4096, 512);

    for (int t = 0; t < 32; t++) {
        k_gates<<<128, 256>>>(Whh, t);
        k_zrt<<<320, 256>>>(Wz, Wh, Wr);
        k_hh<<<128, 256>>>(Wh, bh, t);
    }

    // logits = hs @ Wo.T + bo:  M=1024, N=32000, K=1024
    gemm_f32x2<<<dim3(8, 250), 256>>>((const float*)p_hs, Wo, bo, out,
                                      1024, 32000, 1024);

    k_tail<<<128, 256>>>(out);
}

// round 2
// speedup vs baseline: 1.0010x; 1.0010x over previous
#include <cuda_runtime.h>
#include <math.h>

typedef unsigned long long u64;

// ---------------- scratch (device globals; no allocs allowed) ----------------
__device__ float g_weT[512 * 32];        // we transposed [e][b]
__device__ float g_se[1024 * 512];       // se [(t*32+b)][e]
__device__ float g_bsum[4096];           // bih + bhh
__device__ float g_gx[1024 * 4096];      // se @ Wih.T + bsum   [(t*32+b)][4H]
__device__ float g_hT[1024 * 32];        // h  [j][b]
__device__ float g_cT[1024 * 32];        // c  [j][b]
__device__ float g_h1T[1024 * 32];       // post-LSTM h [j][b]
__device__ float g_zcT[1024 * 32];       // we-part of z preact [j][b]
__device__ float g_rcT[512 * 32];        // we-part of r preact [e][b]
__device__ float g_zT[1024 * 32];        // z [j][b]
__device__ float g_t1T[1024 * 32];       // h1 @ Wh_h.T [j][b]
__device__ float g_rwT[512 * 32];        // r * we [e][b]
__device__ float g_hs[1024 * 1024];      // hs [(t*32+b)][j]  (GEMM A)

__device__ __forceinline__ float sigf(float x) { return 1.f / (1.f + expf(-x)); }

__device__ __forceinline__ u64 fma2(u64 a, u64 b, u64 c) {
    u64 d;
    asm("fma.rn.f32x2 %0, %1, %2, %3;" : "=l"(d) : "l"(a), "l"(b), "l"(c));
    return d;
}

// ---------------- gather: we (transposed), se, bias sum ----------------
__global__ void k_gather(const int* __restrict__ word, const int* __restrict__ seq,
                         const float* __restrict__ emb,
                         const float* __restrict__ bih, const float* __restrict__ bhh)
{
    int idx = blockIdx.x * blockDim.x + threadIdx.x;
    if (idx < 1024 * 512) {
        int m = idx >> 9, e = idx & 511;
        g_se[idx] = emb[(size_t)seq[m] * 512 + e];
    }
    if (idx < 512 * 32) {
        int e = idx >> 5, b = idx & 31;
        g_weT[idx] = emb[(size_t)word[b] * 512 + e];
    }
    if (idx < 4096) g_bsum[idx] = bih[idx] + bhh[idx];
}

// ---------------- prep: h0 (-> h,c), zc, rc ; one warp per output row ----------------
__global__ void k_prep(const float* __restrict__ Wl, const float* __restrict__ bl,
                       const float* __restrict__ Wz, const float* __restrict__ bz,
                       const float* __restrict__ Wr, const float* __restrict__ br)
{
    int w = (blockIdx.x * blockDim.x + threadIdx.x) >> 5;   // 0..2559
    int lane = threadIdx.x & 31;                            // = b
    const float* wr;
    float bias;
    if (w < 1024)      { wr = Wl + (size_t)w * 512;            bias = bl[w]; }
    else if (w < 2048) { wr = Wz + (size_t)(w - 1024) * 1536;  bias = bz[w - 1024]; }
    else               { wr = Wr + (size_t)(w - 2048) * 1536;  bias = br[w - 2048]; }
    float acc = 0.f;
#pragma unroll 4
    for (int e = 0; e < 512; e += 4) {
        float4 wv = *(const float4*)(wr + e);
        acc += g_weT[(e + 0) * 32 + lane] * wv.x + g_weT[(e + 1) * 32 + lane] * wv.y
             + g_weT[(e + 2) * 32 + lane] * wv.z + g_weT[(e + 3) * 32 + lane] * wv.w;
    }
    acc += bias;
    if (w < 1024)      { g_hT[w * 32 + lane] = acc; g_cT[w * 32 + lane] = acc; }
    else if (w < 2048) { g_zcT[(w - 1024) * 32 + lane] = acc; }
    else               { g_rcT[(w - 2048) * 32 + lane] = acc; }
}

// ---------------- tiled f32x2 GEMM: C[M,N] = A[M,K] * B[N,K]^T + bias[N] ----------------
// BM=BN=128, BK=16, 256 threads, 8x8 per thread (n in f32x2 pairs, A duplicated in smem)
__global__ void __launch_bounds__(256) gemm_f32x2(
    const float* __restrict__ A, const float* __restrict__ B,
    const float* __restrict__ bias, float* __restrict__ C,
    int M, int N, int K)
{
    const int BK = 16;
    __shared__ __align__(16) float As[16][256];  // duplicated pairs: As[k][2m],[2m+1]
    __shared__ __align__(16) float Bs[16][128];

    const int tid = threadIdx.x;
    const int mBase = blockIdx.x * 128;
    const int nBase = blockIdx.y * 128;

    const int lm  = tid >> 2;        // 0..63 (row within tile; also +64)
    const int lk4 = (tid & 3) * 4;   // 0,4,8,12

    const float* Aptr = A + (size_t)(mBase + lm) * K + lk4;
    const float* Bptr = B + (size_t)(nBase + lm) * K + lk4;

    const int ty = tid >> 4;     // 0..15
    const int tx = tid & 15;     // 0..15
    const int m0 = ty * 8;
    const int n0 = tx * 8;

    u64 acc[8][4];
#pragma unroll
    for (int i = 0; i < 8; i++)
#pragma unroll
        for (int p = 0; p < 4; p++) acc[i][p] = 0ull;

    // load tile 0
    float4 pa0 = *(const float4*)(Aptr);
    float4 pa1 = *(const float4*)(Aptr + (size_t)64 * K);
    float4 pb0 = *(const float4*)(Bptr);
    float4 pb1 = *(const float4*)(Bptr + (size_t)64 * K);

#define STORE_A(v, m)  { As[lk4+0][2*(m)] = (v).x; As[lk4+0][2*(m)+1] = (v).x; \
                         As[lk4+1][2*(m)] = (v).y; As[lk4+1][2*(m)+1] = (v).y; \
                         As[lk4+2][2*(m)] = (v).z; As[lk4+2][2*(m)+1] = (v).z; \
                         As[lk4+3][2*(m)] = (v).w; As[lk4+3][2*(m)+1] = (v).w; }
#define STORE_B(v, n)  { Bs[lk4+0][(n)] = (v).x; Bs[lk4+1][(n)] = (v).y; \
                         Bs[lk4+2][(n)] = (v).z; Bs[lk4+3][(n)] = (v).w; }

    STORE_A(pa0, lm); STORE_A(pa1, lm + 64);
    STORE_B(pb0, lm); STORE_B(pb1, lm + 64);
    __syncthreads();

    int ktile = 0;
    while (true) {
        ktile += BK;
        bool more = (ktile < K);
        if (more) {
            pa0 = *(const float4*)(Aptr + ktile);
            pa1 = *(const float4*)(Aptr + (size_t)64 * K + ktile);
            pb0 = *(const float4*)(Bptr + ktile);
            pb1 = *(const float4*)(Bptr + (size_t)64 * K + ktile);
        }
#pragma unroll
        for (int k = 0; k < BK; k++) {
            u64 a[8], b[4];
            const u64* ap = reinterpret_cast<const u64*>(&As[k][2 * m0]);
#pragma unroll
            for (int i = 0; i < 8; i++) a[i] = ap[i];
            const u64* bp = reinterpret_cast<const u64*>(&Bs[k][n0]);
#pragma unroll
            for (int p = 0; p < 4; p++) b[p] = bp[p];
#pragma unroll
            for (int i = 0; i < 8; i++)
#pragma unroll
                for (int p = 0; p < 4; p++) acc[i][p] = fma2(a[i], b[p], acc[i][p]);
        }
        if (!more) break;
        __syncthreads();
        STORE_A(pa0, lm); STORE_A(pa1, lm + 64);
        STORE_B(pb0, lm); STORE_B(pb1, lm + 64);
        __syncthreads();
    }

#pragma unroll
    for (int i = 0; i < 8; i++) {
        float* crow = C + (size_t)(mBase + m0 + i) * N + nBase + n0;
#pragma unroll
        for (int p = 0; p < 4; p++) {
            float2 v = *reinterpret_cast<float2*>(&acc[i][p]);
            if (bias) {
                v.x += bias[nBase + n0 + 2 * p];
                v.y += bias[nBase + n0 + 2 * p + 1];
            }
            *reinterpret_cast<float2*>(crow + 2 * p) = v;
        }
    }
#undef STORE_A
#undef STORE_B
}

// ---------------- per-step: gates GEMV (4 rows/warp) + LSTM pointwise ----------------
__global__ void k_gates(const float* __restrict__ Whh, int t)
{
    int j = (blockIdx.x * blockDim.x + threadIdx.x) >> 5;   // 0..1023
    int lane = threadIdx.x & 31;                            // = b
    const float* Wi  = Whh + (size_t)j * 1024;
    const float* Wf  = Wi + (size_t)1024 * 1024;
    const float* Wg  = Wf + (size_t)1024 * 1024;
    const float* Wo_ = Wg + (size_t)1024 * 1024;
    float ai = 0.f, af = 0.f, ag = 0.f, ao = 0.f;
#pragma unroll 4
    for (int k = 0; k < 1024; k += 4) {
        float h0v = g_hT[(k + 0) * 32 + lane];
        float h1v = g_hT[(k + 1) * 32 + lane];
        float h2v = g_hT[(k + 2) * 32 + lane];
        float h3v = g_hT[(k + 3) * 32 + lane];
        float4 wi = *(const float4*)(Wi + k);
        float4 wf = *(const float4*)(Wf + k);
        float4 wg = *(const float4*)(Wg + k);
        float4 wo = *(const float4*)(Wo_ + k);
        ai += h0v * wi.x + h1v * wi.y + h2v * wi.z + h3v * wi.w;
        af += h0v * wf.x + h1v * wf.y + h2v * wf.z + h3v * wf.w;
        ag += h0v * wg.x + h1v * wg.y + h2v * wg.z + h3v * wg.w;
        ao += h0v * wo.x + h1v * wo.y + h2v * wo.z + h3v * wo.w;
    }
    const float* gx = g_gx + (size_t)(t * 32 + lane) * 4096 + j;
    float gi = gx[0] + ai;
    float gf = gx[1024] + af;
    float gg = gx[2048] + ag;
    float go = gx[3072] + ao;
    float co = g_cT[j * 32 + lane];
    float cn = sigf(gf) * co + sigf(gi) * tanhf(gg);
    g_cT[j * 32 + lane] = cn;
    g_h1T[j * 32 + lane] = sigf(go) * tanhf(cn);
}

// ---------------- per-step: z, t1 = h1@Wh_h.T, r*we ----------------
__global__ void k_zrt(const float* __restrict__ Wz, const float* __restrict__ Wh,
                      const float* __restrict__ Wr)
{
    int w = (blockIdx.x * blockDim.x + threadIdx.x) >> 5;   // 0..2559
    int lane = threadIdx.x & 31;
    const float* wr;
    if (w < 1024)      wr = Wz + (size_t)w * 1536 + 512;
    else if (w < 2048) wr = Wh + (size_t)(w - 1024) * 1536 + 512;
    else               wr = Wr + (size_t)(w - 2048) * 1536 + 512;
    float acc = 0.f;
#pragma unroll 8
    for (int k = 0; k < 1024; k += 4) {
        float4 wv = *(const float4*)(wr + k);
        acc += g_h1T[(k + 0) * 32 + lane] * wv.x + g_h1T[(k + 1) * 32 + lane] * wv.y
             + g_h1T[(k + 2) * 32 + lane] * wv.z + g_h1T[(k + 3) * 32 + lane] * wv.w;
    }
    if (w < 1024) {
        g_zT[w * 32 + lane] = sigf(g_zcT[w * 32 + lane] + acc);
    } else if (w < 2048) {
        g_t1T[(w - 1024) * 32 + lane] = acc;
    } else {
        int e = w - 2048;
        float r = sigf(g_rcT[e * 32 + lane] + acc);
        g_rwT[e * 32 + lane] = r * g_weT[e * 32 + lane];
    }
}

// ---------------- per-step: hh, final h update, write hs ----------------
__global__ void k_hh(const float* __restrict__ Wh, const float* __restrict__ bh, int t)
{
    int j = (blockIdx.x * blockDim.x + threadIdx.x) >> 5;   // 0..1023
    int lane = threadIdx.x & 31;
    const float* wr = Wh + (size_t)j * 1536;
    float acc = 0.f;
#pragma unroll 8
    for (int e = 0; e < 512; e += 4) {
        float4 wv = *(const float4*)(wr + e);
        acc += g_rwT[(e + 0) * 32 + lane] * wv.x + g_rwT[(e + 1) * 32 + lane] * wv.y
             + g_rwT[(e + 2) * 32 + lane] * wv.z + g_rwT[(e + 3) * 32 + lane] * wv.w;
    }
    float hh = tanhf(g_t1T[j * 32 + lane] + acc + bh[j]);
    float z  = g_zT[j * 32 + lane];
    float h1 = g_h1T[j * 32 + lane];
    float hn = (1.f - z) * h1 + z * hh;
    g_hT[j * 32 + lane] = hn;
    g_hs[(size_t)(t * 32 + lane) * 1024 + j] = hn;
}

// ---------------- tail: hf, cf into output ----------------
__global__ void k_tail(float* __restrict__ out)
{
    int idx = blockIdx.x * blockDim.x + threadIdx.x;   // < 32768
    int b = idx >> 10, j = idx & 1023;
    out[32768000 + idx]         = g_hT[j * 32 + b];
    out[32768000 + 32768 + idx] = g_cT[j * 32 + b];
}

// ---------------- launch ----------------
extern "C" void kernel_launch(void* const* d_in, const int* in_sizes, int n_in,
                              void* d_out, int out_size)
{
    const int*   word = (const int*)d_in[0];
    const int*   seq  = (const int*)d_in[1];
    const float* emb  = (const float*)d_in[2];
    const float* Wl   = (const float*)d_in[3];
    const float* bl   = (const float*)d_in[4];
    const float* Wih  = (const float*)d_in[5];
    const float* Whh  = (const float*)d_in[6];
    const float* bih  = (const float*)d_in[7];
    const float* bhh  = (const float*)d_in[8];
    const float* Wz   = (const float*)d_in[9];
    const float* bz   = (const float*)d_in[10];
    const float* Wr   = (const float*)d_in[11];
    const float* br   = (const float*)d_in[12];
    const float* Wh   = (const float*)d_in[13];
    const float* bh   = (const float*)d_in[14];
    const float* Wo   = (const float*)d_in[15];
    const float* bo   = (const float*)d_in[16];
    float* out = (float*)d_out;

    void *p_se, *p_gx, *p_bsum, *p_hs;
    cudaGetSymbolAddress(&p_se, g_se);
    cudaGetSymbolAddress(&p_gx, g_gx);
    cudaGetSymbolAddress(&p_bsum, g_bsum);
    cudaGetSymbolAddress(&p_hs, g_hs);

    k_gather<<<2048, 256>>>(word, seq, emb, bih, bhh);
    k_prep<<<320, 256>>>(Wl, bl, Wz, bz, Wr, br);

    // gx = se @ Wih.T + (bih+bhh):  M=1024, N=4096, K=512
    gemm_f32x2<<<dim3(8, 32), 256>>>((const float*)p_se, Wih, (const float*)p_bsum,
                                     (float*)p_gx, 1024, 4096, 512);

    for (int t = 0; t < 32; t++) {
        k_gates<<<128, 256>>>(Whh, t);
        k_zrt<<<320, 256>>>(Wz, Wh, Wr);
        k_hh<<<128, 256>>>(Wh, bh, t);
    }

    // logits = hs @ Wo.T + bo:  M=1024, N=32000, K=1024
    gemm_f32x2<<<dim3(8, 250), 256>>>((const float*)p_hs, Wo, bo, out,
                                      1024, 32000, 1024);

    k_tail<<<128, 256>>>(out);
}

// round 3
// speedup vs baseline: 2.0721x; 2.0700x over previous
#include <cuda_runtime.h>
#include <math.h>

typedef unsigned long long u64;

// ---------------- scratch (device globals; no allocs allowed) ----------------
__device__ float g_weT[512 * 32];        // we transposed [e][b]
__device__ float g_se[1024 * 512];       // se [(t*32+b)][e]
__device__ float g_bsum[4096];           // bih + bhh
__device__ float g_gx[1024 * 4096];      // se @ Wih.T + bsum   [(t*32+b)][4H]
__device__ float g_hT[1024 * 32];        // h  [j][b]
__device__ float g_cT[1024 * 32];        // c  [j][b]
__device__ float g_h1T[1024 * 32];       // post-LSTM h [j][b]
__device__ float g_zcT[1024 * 32];       // we-part of z preact [j][b]
__device__ float g_rcT[512 * 32];        // we-part of r preact [e][b]
__device__ float g_zT[1024 * 32];        // z [j][b]
__device__ float g_t1T[1024 * 32];       // h1 @ Wh_h.T [j][b]
__device__ float g_rwT[512 * 32];        // r * we [e][b]
__device__ float g_hs[1024 * 1024];      // hs [(t*32+b)][j]  (GEMM A)

__device__ __forceinline__ float sigf(float x) { return 1.f / (1.f + expf(-x)); }

__device__ __forceinline__ u64 fma2(u64 a, u64 b, u64 c) {
    u64 d;
    asm("fma.rn.f32x2 %0, %1, %2, %3;" : "=l"(d) : "l"(a), "l"(b), "l"(c));
    return d;
}

// ---------------- gather: we (transposed), se, bias sum ----------------
__global__ void k_gather(const int* __restrict__ word, const int* __restrict__ seq,
                         const float* __restrict__ emb,
                         const float* __restrict__ bih, const float* __restrict__ bhh)
{
    int idx = blockIdx.x * blockDim.x + threadIdx.x;
    if (idx < 1024 * 512) {
        int m = idx >> 9, e = idx & 511;
        g_se[idx] = emb[(size_t)seq[m] * 512 + e];
    }
    if (idx < 512 * 32) {
        int e = idx >> 5, b = idx & 31;
        g_weT[idx] = emb[(size_t)word[b] * 512 + e];
    }
    if (idx < 4096) g_bsum[idx] = bih[idx] + bhh[idx];
}

// ================= shared micro-GEMM core =================
// Block: 256 threads = 4 k-groups x 64 threads.
// Computes Red[kg][32 rows][32 cols] partials for C = A[32,K] * X[K,32],
// where each k-group handles K/4 (= T*16) of the K dim.
// A rows are given per-thread via arow (already offset to this kg's k-base);
// X is [k][b] row-major 32 floats/row, brow = X + kg*(T*16)*32.
// Per-thread roles (s = tid & 63):
//   A loader: r = s>>1 (tile row), kofs = (s&1)*8   -> 2x float4 per tile
//   B loader: bk = s>>2 (k row),  bofs = (s&3)*8    -> 2x float4 per tile
//   compute:  mthr = s>>3 (4 rows), nthr = s&7 (4 cols as 2 f32x2 pairs)
template<int T>
__device__ __forceinline__ void gemm_core(
    float (*As)[16][64], float (*Bs)[16][32], float (*Red)[32][32],
    const float* arow, const float* brow, int kg, int s)
{
    const int r = s >> 1, kofs = (s & 1) * 8;
    const int bk = s >> 2, bofs = (s & 3) * 8;
    const int mthr = s >> 3, nthr = s & 7;
    const int m0 = mthr * 4, n0 = nthr * 4;

    u64 acc[4][2];
#pragma unroll
    for (int i = 0; i < 4; i++) { acc[i][0] = 0ull; acc[i][1] = 0ull; }

    const float* aP = arow + kofs;
    const float* bP = brow + bk * 32 + bofs;

    float4 a0 = *(const float4*)aP;
    float4 a1 = *(const float4*)(aP + 4);
    float4 b0 = *(const float4*)bP;
    float4 b1 = *(const float4*)(bP + 4);

#pragma unroll 1
    for (int t = 0; t < T; t++) {
        {   // stage tile (A pair-duplicated for f32x2)
            float va[8] = {a0.x, a0.y, a0.z, a0.w, a1.x, a1.y, a1.z, a1.w};
#pragma unroll
            for (int i = 0; i < 8; i++) {
                float2 d = make_float2(va[i], va[i]);
                *(float2*)&As[kg][kofs + i][2 * r] = d;
            }
            *(float4*)&Bs[kg][bk][bofs]     = b0;
            *(float4*)&Bs[kg][bk][bofs + 4] = b1;
        }
        __syncthreads();
        if (t + 1 < T) {   // register prefetch of next tile
            aP += 16; bP += 512;
            a0 = *(const float4*)aP;
            a1 = *(const float4*)(aP + 4);
            b0 = *(const float4*)bP;
            b1 = *(const float4*)(bP + 4);
        }
#pragma unroll
        for (int k = 0; k < 16; k++) {
            float4 av0 = *(const float4*)&As[kg][k][2 * m0];
            float4 av1 = *(const float4*)&As[kg][k][2 * m0 + 4];
            float4 bv  = *(const float4*)&Bs[kg][k][n0];
            const u64* ap0 = (const u64*)&av0;
            const u64* ap1 = (const u64*)&av1;
            const u64* bp  = (const u64*)&bv;
            acc[0][0] = fma2(ap0[0], bp[0], acc[0][0]);
            acc[0][1] = fma2(ap0[0], bp[1], acc[0][1]);
            acc[1][0] = fma2(ap0[1], bp[0], acc[1][0]);
            acc[1][1] = fma2(ap0[1], bp[1], acc[1][1]);
            acc[2][0] = fma2(ap1[0], bp[0], acc[2][0]);
            acc[2][1] = fma2(ap1[0], bp[1], acc[2][1]);
            acc[3][0] = fma2(ap1[1], bp[0], acc[3][0]);
            acc[3][1] = fma2(ap1[1], bp[1], acc[3][1]);
        }
        __syncthreads();
    }
#pragma unroll
    for (int i = 0; i < 4; i++) {
        *(float2*)&Red[kg][m0 + i][n0]     = *(float2*)&acc[i][0];
        *(float2*)&Red[kg][m0 + i][n0 + 2] = *(float2*)&acc[i][1];
    }
    __syncthreads();
}

#define STEP_SMEM \
    __shared__ __align__(16) float As[4][16][64]; \
    __shared__ __align__(16) float Bs[4][16][32]; \
    __shared__ float Red[4][32][32];

// ---------------- prep: h0 (-> h,c), zc, rc ----------------
__global__ void __launch_bounds__(256) k_prep2(
    const float* __restrict__ Wl, const float* __restrict__ bl,
    const float* __restrict__ Wz, const float* __restrict__ bz,
    const float* __restrict__ Wr, const float* __restrict__ br)
{
    STEP_SMEM
    const int tid = threadIdx.x;
    const int kg = tid >> 6, s = tid & 63;
    const int mbase = blockIdx.x * 32;
    const int w = mbase + (s >> 1);
    const float* arow;
    if (w < 1024)      arow = Wl + (size_t)w * 512;
    else if (w < 2048) arow = Wz + (size_t)(w - 1024) * 1536;
    else               arow = Wr + (size_t)(w - 2048) * 1536;
    arow += kg * 128;
    const float* brow = g_weT + kg * 128 * 32;
    gemm_core<8>(As, Bs, Red, arow, brow, kg, s);

    const int m = tid >> 3, nq = (tid & 7) * 4;
    const int wo = mbase + m;
    float4 v0 = *(float4*)&Red[0][m][nq];
    float4 v1 = *(float4*)&Red[1][m][nq];
    float4 v2 = *(float4*)&Red[2][m][nq];
    float4 v3 = *(float4*)&Red[3][m][nq];
    float v[4] = { v0.x + v1.x + v2.x + v3.x, v0.y + v1.y + v2.y + v3.y,
                   v0.z + v1.z + v2.z + v3.z, v0.w + v1.w + v2.w + v3.w };
    if (wo < 1024) {
        float bb = bl[wo];
#pragma unroll
        for (int q = 0; q < 4; q++) {
            float h0 = v[q] + bb;
            g_hT[wo * 32 + nq + q] = h0;
            g_cT[wo * 32 + nq + q] = h0;
        }
    } else if (wo < 2048) {
        int i = wo - 1024; float bb = bz[i];
#pragma unroll
        for (int q = 0; q < 4; q++) g_zcT[i * 32 + nq + q] = v[q] + bb;
    } else {
        int e = wo - 2048; float bb = br[e];
#pragma unroll
        for (int q = 0; q < 4; q++) g_rcT[e * 32 + nq + q] = v[q] + bb;
    }
}

// ---------------- step phase 1: gates GEMM + LSTM pointwise ----------------
// Block handles 8 j x 4 gates (32 rows). Tile row x -> W row = ((x&3)<<10) + jbase + (x>>2)
__global__ void __launch_bounds__(256) k_step1(const float* __restrict__ Whh, int t)
{
    STEP_SMEM
    const int tid = threadIdx.x;
    const int kg = tid >> 6, s = tid & 63;
    const int jbase = blockIdx.x * 8;
    const int r = s >> 1;
    const int wrow = ((r & 3) << 10) + jbase + (r >> 2);
    const float* arow = Whh + (size_t)wrow * 1024 + kg * 256;
    const float* brow = g_hT + kg * 256 * 32;
    gemm_core<16>(As, Bs, Red, arow, brow, kg, s);

    const int jloc = tid >> 5, b = tid & 31;
    const int j = jbase + jloc;
    float g4[4];
#pragma unroll
    for (int g = 0; g < 4; g++) {
        int m = jloc * 4 + g;
        g4[g] = Red[0][m][b] + Red[1][m][b] + Red[2][m][b] + Red[3][m][b];
    }
    const float* gx = g_gx + (size_t)(t * 32 + b) * 4096 + j;
    float gi = gx[0]    + g4[0];
    float gf = gx[1024] + g4[1];
    float gg = gx[2048] + g4[2];
    float go = gx[3072] + g4[3];
    float c  = g_cT[j * 32 + b];
    float cn = sigf(gf) * c + sigf(gi) * tanhf(gg);
    g_cT[j * 32 + b]  = cn;
    g_h1T[j * 32 + b] = sigf(go) * tanhf(cn);
}

// ---------------- step phase 2: z, t1, r*we ----------------
__global__ void __launch_bounds__(256) k_step2(
    const float* __restrict__ Wz, const float* __restrict__ Wh,
    const float* __restrict__ Wr)
{
    STEP_SMEM
    const int tid = threadIdx.x;
    const int kg = tid >> 6, s = tid & 63;
    const int mbase = blockIdx.x * 32;
    const int w = mbase + (s >> 1);
    const float* arow;
    if (w < 1024)      arow = Wz + (size_t)w * 1536 + 512;
    else if (w < 2048) arow = Wh + (size_t)(w - 1024) * 1536 + 512;
    else               arow = Wr + (size_t)(w - 2048) * 1536 + 512;
    arow += kg * 256;
    const float* brow = g_h1T + kg * 256 * 32;
    gemm_core<16>(As, Bs, Red, arow, brow, kg, s);

    const int m = tid >> 3, nq = (tid & 7) * 4;
    const int wo = mbase + m;
    float4 v0 = *(float4*)&Red[0][m][nq];
    float4 v1 = *(float4*)&Red[1][m][nq];
    float4 v2 = *(float4*)&Red[2][m][nq];
    float4 v3 = *(float4*)&Red[3][m][nq];
    float v[4] = { v0.x + v1.x + v2.x + v3.x, v0.y + v1.y + v2.y + v3.y,
                   v0.z + v1.z + v2.z + v3.z, v0.w + v1.w + v2.w + v3.w };
    if (wo < 1024) {
#pragma unroll
        for (int q = 0; q < 4; q++)
            g_zT[wo * 32 + nq + q] = sigf(g_zcT[wo * 32 + nq + q] + v[q]);
    } else if (wo < 2048) {
        int j = wo - 1024;
#pragma unroll
        for (int q = 0; q < 4; q++) g_t1T[j * 32 + nq + q] = v[q];
    } else {
        int e = wo - 2048;
#pragma unroll
        for (int q = 0; q < 4; q++) {
            float rr = sigf(g_rcT[e * 32 + nq + q] + v[q]);
            g_rwT[e * 32 + nq + q] = rr * g_weT[e * 32 + nq + q];
        }
    }
}

// ---------------- step phase 3: hh GEMM + h update ----------------
__global__ void __launch_bounds__(256) k_step3(
    const float* __restrict__ Wh, const float* __restrict__ bh, int t)
{
    STEP_SMEM
    const int tid = threadIdx.x;
    const int kg = tid >> 6, s = tid & 63;
    const int jbase = blockIdx.x * 32;
    const float* arow = Wh + (size_t)(jbase + (s >> 1)) * 1536 + kg * 128;
    const float* brow = g_rwT + kg * 128 * 32;
    gemm_core<8>(As, Bs, Red, arow, brow, kg, s);

    const int b = tid >> 3, jq = (tid & 7) * 4;
#pragma unroll
    for (int q = 0; q < 4; q++) {
        int m = jq + q, j = jbase + m;
        float v = Red[0][m][b] + Red[1][m][b] + Red[2][m][b] + Red[3][m][b];
        float hh = tanhf(g_t1T[j * 32 + b] + v + bh[j]);
        float z  = g_zT[j * 32 + b];
        float h1 = g_h1T[j * 32 + b];
        float hn = (1.f - z) * h1 + z * hh;
        g_hT[j * 32 + b] = hn;
        g_hs[(size_t)(t * 32 + b) * 1024 + j] = hn;
    }
}

// ---------------- tiled f32x2 GEMM: C[M,N] = A[M,K] * B[N,K]^T + bias[N] ----------------
__global__ void __launch_bounds__(256) gemm_f32x2(
    const float* __restrict__ A, const float* __restrict__ B,
    const float* __restrict__ bias, float* __restrict__ C,
    int M, int N, int K)
{
    const int BK = 16;
    __shared__ __align__(16) float As[16][256];
    __shared__ __align__(16) float Bs[16][128];

    const int tid = threadIdx.x;
    const int mBase = blockIdx.x * 128;
    const int nBase = blockIdx.y * 128;

    const int lm  = tid >> 2;
    const int lk4 = (tid & 3) * 4;

    const float* Aptr = A + (size_t)(mBase + lm) * K + lk4;
    const float* Bptr = B + (size_t)(nBase + lm) * K + lk4;

    const int ty = tid >> 4;
    const int tx = tid & 15;
    const int m0 = ty * 8;
    const int n0 = tx * 8;

    u64 acc[8][4];
#pragma unroll
    for (int i = 0; i < 8; i++)
#pragma unroll
        for (int p = 0; p < 4; p++) acc[i][p] = 0ull;

    float4 pa0 = *(const float4*)(Aptr);
    float4 pa1 = *(const float4*)(Aptr + (size_t)64 * K);
    float4 pb0 = *(const float4*)(Bptr);
    float4 pb1 = *(const float4*)(Bptr + (size_t)64 * K);

#define STORE_A(v, m)  { As[lk4+0][2*(m)] = (v).x; As[lk4+0][2*(m)+1] = (v).x; \
                         As[lk4+1][2*(m)] = (v).y; As[lk4+1][2*(m)+1] = (v).y; \
                         As[lk4+2][2*(m)] = (v).z; As[lk4+2][2*(m)+1] = (v).z; \
                         As[lk4+3][2*(m)] = (v).w; As[lk4+3][2*(m)+1] = (v).w; }
#define STORE_B(v, n)  { Bs[lk4+0][(n)] = (v).x; Bs[lk4+1][(n)] = (v).y; \
                         Bs[lk4+2][(n)] = (v).z; Bs[lk4+3][(n)] = (v).w; }

    STORE_A(pa0, lm); STORE_A(pa1, lm + 64);
    STORE_B(pb0, lm); STORE_B(pb1, lm + 64);
    __syncthreads();

    int ktile = 0;
    while (true) {
        ktile += BK;
        bool more = (ktile < K);
        if (more) {
            pa0 = *(const float4*)(Aptr + ktile);
            pa1 = *(const float4*)(Aptr + (size_t)64 * K + ktile);
            pb0 = *(const float4*)(Bptr + ktile);
            pb1 = *(const float4*)(Bptr + (size_t)64 * K + ktile);
        }
#pragma unroll
        for (int k = 0; k < BK; k++) {
            u64 a[8], b[4];
            const u64* ap = reinterpret_cast<const u64*>(&As[k][2 * m0]);
#pragma unroll
            for (int i = 0; i < 8; i++) a[i] = ap[i];
            const u64* bp = reinterpret_cast<const u64*>(&Bs[k][n0]);
#pragma unroll
            for (int p = 0; p < 4; p++) b[p] = bp[p];
#pragma unroll
            for (int i = 0; i < 8; i++)
#pragma unroll
                for (int p = 0; p < 4; p++) acc[i][p] = fma2(a[i], b[p], acc[i][p]);
        }
        if (!more) break;
        __syncthreads();
        STORE_A(pa0, lm); STORE_A(pa1, lm + 64);
        STORE_B(pb0, lm); STORE_B(pb1, lm + 64);
        __syncthreads();
    }

#pragma unroll
    for (int i = 0; i < 8; i++) {
        float* crow = C + (size_t)(mBase + m0 + i) * N + nBase + n0;
#pragma unroll
        for (int p = 0; p < 4; p++) {
            float2 v = *reinterpret_cast<float2*>(&acc[i][p]);
            if (bias) {
                v.x += bias[nBase + n0 + 2 * p];
                v.y += bias[nBase + n0 + 2 * p + 1];
            }
            *reinterpret_cast<float2*>(crow + 2 * p) = v;
        }
    }
#undef STORE_A
#undef STORE_B
}

// ---------------- tail: hf, cf into output ----------------
__global__ void k_tail(float* __restrict__ out)
{
    int idx = blockIdx.x * blockDim.x + threadIdx.x;   // < 32768
    int b = idx >> 10, j = idx & 1023;
    out[32768000 + idx]         = g_hT[j * 32 + b];
    out[32768000 + 32768 + idx] = g_cT[j * 32 + b];
}

// ---------------- launch ----------------
extern "C" void kernel_launch(void* const* d_in, const int* in_sizes, int n_in,
                              void* d_out, int out_size)
{
    const int*   word = (const int*)d_in[0];
    const int*   seq  = (const int*)d_in[1];
    const float* emb  = (const float*)d_in[2];
    const float* Wl   = (const float*)d_in[3];
    const float* bl   = (const float*)d_in[4];
    const float* Wih  = (const float*)d_in[5];
    const float* Whh  = (const float*)d_in[6];
    const float* bih  = (const float*)d_in[7];
    const float* bhh  = (const float*)d_in[8];
    const float* Wz   = (const float*)d_in[9];
    const float* bz   = (const float*)d_in[10];
    const float* Wr   = (const float*)d_in[11];
    const float* br   = (const float*)d_in[12];
    const float* Wh   = (const float*)d_in[13];
    const float* bh   = (const float*)d_in[14];
    const float* Wo   = (const float*)d_in[15];
    const float* bo   = (const float*)d_in[16];
    float* out = (float*)d_out;

    void *p_se, *p_gx, *p_bsum, *p_hs;
    cudaGetSymbolAddress(&p_se, g_se);
    cudaGetSymbolAddress(&p_gx, g_gx);
    cudaGetSymbolAddress(&p_bsum, g_bsum);
    cudaGetSymbolAddress(&p_hs, g_hs);

    k_gather<<<2048, 256>>>(word, seq, emb, bih, bhh);
    k_prep2<<<80, 256>>>(Wl, bl, Wz, bz, Wr, br);

    // gx = se @ Wih.T + (bih+bhh):  M=1024, N=4096, K=512
    gemm_f32x2<<<dim3(8, 32), 256>>>((const float*)p_se, Wih, (const float*)p_bsum,
                                     (float*)p_gx, 1024, 4096, 512);

    for (int t = 0; t < 32; t++) {
        k_step1<<<128, 256>>>(Whh, t);
        k_step2<<<80, 256>>>(Wz, Wh, Wr);
        k_step3<<<32, 256>>>(Wh, bh, t);
    }

    // logits = hs @ Wo.T + bo:  M=1024, N=32000, K=1024
    gemm_f32x2<<<dim3(8, 250), 256>>>((const float*)p_hs, Wo, bo, out,
                                      1024, 32000, 1024);

    k_tail<<<128, 256>>>(out);
}

// round 11
// speedup vs baseline: 2.9436x; 1.4206x over previous
#include <cuda_runtime.h>
#include <cuda_bf16.h>
#include <math.h>
#include <stdint.h>

typedef unsigned long long u64;

// ---------------- scratch (device globals; no allocs allowed) ----------------
__device__ float g_weT[512 * 32];        // we transposed [e][b]
__device__ float g_se[1024 * 512];       // se [(t*32+b)][e]
__device__ float g_bsum[4096];           // bih + bhh
__device__ float g_gx[1024 * 4096];      // se @ Wih.T + bsum   [(t*32+b)][4H]
__device__ float g_hT[1024 * 32];        // h  [j][b]
__device__ float g_cT[1024 * 32];        // c  [j][b]
__device__ float g_h1T[1024 * 32];       // post-LSTM h [j][b]
__device__ float g_zcT[1024 * 32];       // we-part of z preact [j][b]
__device__ float g_rcT[512 * 32];        // we-part of r preact [e][b]
__device__ float g_zT[1024 * 32];        // z [j][b]
__device__ float g_t1T[1024 * 32];       // h1 @ Wh_h.T [j][b]
__device__ float g_rwT[512 * 32];        // r * we [e][b]
__device__ float g_hs[1024 * 1024];      // hs [(t*32+b)][j]  (GEMM A)

__device__ __forceinline__ float sigf(float x) { return 1.f / (1.f + expf(-x)); }

__device__ __forceinline__ u64 fma2(u64 a, u64 b, u64 c) {
    u64 d;
    asm("fma.rn.f32x2 %0, %1, %2, %3;" : "=l"(d) : "l"(a), "l"(b), "l"(c));
    return d;
}

__device__ __forceinline__ uint32_t smem_u32(const void* p) {
    uint32_t a;
    asm("{ .reg .u64 t; cvta.to.shared.u64 t, %1; cvt.u32.u64 %0, t; }" : "=r"(a) : "l"(p));
    return a;
}

// ================= mma.sync helpers (base-target PTX, HMMA) =================
__device__ __forceinline__ void ldsm_x4(uint32_t& r0, uint32_t& r1, uint32_t& r2, uint32_t& r3,
                                        uint32_t addr) {
    asm volatile("ldmatrix.sync.aligned.m8n8.x4.shared.b16 {%0,%1,%2,%3}, [%4];"
        : "=r"(r0), "=r"(r1), "=r"(r2), "=r"(r3) : "r"(addr));
}
__device__ __forceinline__ void mma16816(float* c, const uint32_t* a, const uint32_t* b) {
    asm volatile("mma.sync.aligned.m16n8k16.row.col.f32.bf16.bf16.f32 "
        "{%0,%1,%2,%3}, {%4,%5,%6,%7}, {%8,%9}, {%0,%1,%2,%3};"
        : "+f"(c[0]), "+f"(c[1]), "+f"(c[2]), "+f"(c[3])
        : "r"(a[0]), "r"(a[1]), "r"(a[2]), "r"(a[3]), "r"(b[0]), "r"(b[1]));
}

__device__ __forceinline__ uint32_t pack_bf16(float a, float b) {
    uint32_t lo = __bfloat16_as_ushort(__float2bfloat16_rn(a));
    uint32_t hi = __bfloat16_as_ushort(__float2bfloat16_rn(b));
    return lo | (hi << 16);
}
__device__ __forceinline__ void cvt_split(float4 v, uint2& hh, uint2& ll) {
    float hx = __bfloat162float(__float2bfloat16_rn(v.x));
    float hy = __bfloat162float(__float2bfloat16_rn(v.y));
    float hz = __bfloat162float(__float2bfloat16_rn(v.z));
    float hw = __bfloat162float(__float2bfloat16_rn(v.w));
    hh = make_uint2(pack_bf16(v.x, v.y), pack_bf16(v.z, v.w));
    ll = make_uint2(pack_bf16(v.x - hx, v.y - hy), pack_bf16(v.z - hz, v.w - hw));
}

// ======= split-bf16 mma.sync GEMM: C[M,N] = A[M,K] @ B[N,K]^T + bias[N] =======
// grid(x=M/128, y=N/128), 256 threads = 8 warps (4m x 2n), each warp 32x64.
// BK=32 fp32 per chunk; smem tiles bf16 hi/lo, padded row stride 40 elems (80B).
// 3-term accumulation: Ahi*Bhi + Ahi*Blo + Alo*Bhi  (fp32-grade accuracy).
#define RS_EL   40
#define MAT_B   10240            // 128 * 40 * 2 bytes
#define BUF_B   (4 * MAT_B)      // Ahi | Alo | Bhi | Blo
#define GM_SMEM (2 * BUF_B)      // 81920 bytes, double buffered

__global__ void __launch_bounds__(256) gemm_mma(
    const float* __restrict__ A, const float* __restrict__ B,
    const float* __restrict__ bias, float* __restrict__ C,
    int K, int N)
{
    extern __shared__ char smem[];
    const uint32_t sb = smem_u32(smem);
    const int tid = threadIdx.x;
    const int wid = tid >> 5, lane = tid & 31;
    const int wm = wid >> 1, wn = wid & 1;
    const int mBase = blockIdx.x * 128;
    const int nBase = blockIdx.y * 128;
    const int NC = K >> 5;

    float acc[2][8][4];
#pragma unroll
    for (int mt = 0; mt < 2; mt++)
#pragma unroll
        for (int nt = 0; nt < 8; nt++)
#pragma unroll
            for (int q = 0; q < 4; q++) acc[mt][nt][q] = 0.f;

    // loader mapping: 4 float4 each for A and B per thread per chunk
    int lrow[4], lq[4];
#pragma unroll
    for (int i = 0; i < 4; i++) {
        int idx = tid * 4 + i;
        lrow[i] = idx >> 3;
        lq[i] = idx & 7;
    }

    float4 ra[4], rb[4];
#pragma unroll
    for (int i = 0; i < 4; i++) {
        ra[i] = *(const float4*)(A + (size_t)(mBase + lrow[i]) * K + lq[i] * 4);
        rb[i] = *(const float4*)(B + (size_t)(nBase + lrow[i]) * K + lq[i] * 4);
    }
    // stage chunk 0 into buffer 0
#pragma unroll
    for (int i = 0; i < 4; i++) {
        uint2 hh, ll;
        uint32_t off = (uint32_t)(lrow[i] * 80 + lq[i] * 8);
        cvt_split(ra[i], hh, ll);
        *(uint2*)(smem + off) = hh;
        *(uint2*)(smem + MAT_B + off) = ll;
        cvt_split(rb[i], hh, ll);
        *(uint2*)(smem + 2 * MAT_B + off) = hh;
        *(uint2*)(smem + 3 * MAT_B + off) = ll;
    }
    __syncthreads();

    const uint32_t a_ls = (uint32_t)(wm * 32 + (lane & 15)) * 80 + (lane >> 4) * 16;
    const uint32_t b_ls = (uint32_t)(wn * 64 + (lane & 15)) * 80 + (lane >> 4) * 16;

    for (int c = 0; c < NC; c++) {
        const int p = c & 1;
        const uint32_t bufb = sb + p * BUF_B;

        if (c + 1 < NC) {   // issue global loads early; latency hidden by MMAs
            const int kc = (c + 1) * 32;
#pragma unroll
            for (int i = 0; i < 4; i++) {
                ra[i] = *(const float4*)(A + (size_t)(mBase + lrow[i]) * K + kc + lq[i] * 4);
                rb[i] = *(const float4*)(B + (size_t)(nBase + lrow[i]) * K + kc + lq[i] * 4);
            }
        }

#pragma unroll
        for (int ks = 0; ks < 2; ks++) {
            uint32_t ahi[2][4], alo[2][4];
#pragma unroll
            for (int mt = 0; mt < 2; mt++) {
                uint32_t off = a_ls + mt * 16 * 80 + ks * 32;
                ldsm_x4(ahi[mt][0], ahi[mt][1], ahi[mt][2], ahi[mt][3], bufb + off);
                ldsm_x4(alo[mt][0], alo[mt][1], alo[mt][2], alo[mt][3], bufb + MAT_B + off);
            }
            uint32_t bhi[8][2], blo[8][2];
#pragma unroll
            for (int g = 0; g < 4; g++) {
                uint32_t off = b_ls + g * 16 * 80 + ks * 32;
                uint32_t r0, r1, r2, r3;
                ldsm_x4(r0, r1, r2, r3, bufb + 2 * MAT_B + off);
                bhi[2 * g][0] = r0; bhi[2 * g][1] = r2;
                bhi[2 * g + 1][0] = r1; bhi[2 * g + 1][1] = r3;
                ldsm_x4(r0, r1, r2, r3, bufb + 3 * MAT_B + off);
                blo[2 * g][0] = r0; blo[2 * g][1] = r2;
                blo[2 * g + 1][0] = r1; blo[2 * g + 1][1] = r3;
            }
#pragma unroll
            for (int mt = 0; mt < 2; mt++)
#pragma unroll
                for (int nt = 0; nt < 8; nt++) {
                    mma16816(acc[mt][nt], ahi[mt], bhi[nt]);
                    mma16816(acc[mt][nt], ahi[mt], blo[nt]);
                    mma16816(acc[mt][nt], alo[mt], bhi[nt]);
                }
        }

        if (c + 1 < NC) {   // stage chunk c+1 into the other buffer
            char* dst = smem + (p ^ 1) * BUF_B;
#pragma unroll
            for (int i = 0; i < 4; i++) {
                uint2 hh, ll;
                uint32_t off = (uint32_t)(lrow[i] * 80 + lq[i] * 8);
                cvt_split(ra[i], hh, ll);
                *(uint2*)(dst + off) = hh;
                *(uint2*)(dst + MAT_B + off) = ll;
                cvt_split(rb[i], hh, ll);
                *(uint2*)(dst + 2 * MAT_B + off) = hh;
                *(uint2*)(dst + 3 * MAT_B + off) = ll;
            }
        }
        __syncthreads();
    }

    // epilogue: direct coalesced float2 stores with bias
#pragma unroll
    for (int mt = 0; mt < 2; mt++) {
        const int row0 = mBase + wm * 32 + mt * 16 + (lane >> 2);
#pragma unroll
        for (int nt = 0; nt < 8; nt++) {
            const int col = nBase + wn * 64 + nt * 8 + (lane & 3) * 2;
            float2 bv = *(const float2*)(bias + col);
            float2 o0 = make_float2(acc[mt][nt][0] + bv.x, acc[mt][nt][1] + bv.y);
            float2 o1 = make_float2(acc[mt][nt][2] + bv.x, acc[mt][nt][3] + bv.y);
            *(float2*)(C + (size_t)row0 * N + col) = o0;
            *(float2*)(C + (size_t)(row0 + 8) * N + col) = o1;
        }
    }
}

// ---------------- gather: we (transposed), se, bias sum ----------------
__global__ void k_gather(const int* __restrict__ word, const int* __restrict__ seq,
                         const float* __restrict__ emb,
                         const float* __restrict__ bih, const float* __restrict__ bhh)
{
    int idx = blockIdx.x * blockDim.x + threadIdx.x;
    if (idx < 1024 * 512) {
        int m = idx >> 9, e = idx & 511;
        g_se[idx] = emb[(size_t)seq[m] * 512 + e];
    }
    if (idx < 512 * 32) {
        int e = idx >> 5, b = idx & 31;
        g_weT[idx] = emb[(size_t)word[b] * 512 + e];
    }
    if (idx < 4096) g_bsum[idx] = bih[idx] + bhh[idx];
}

// ================= shared micro-GEMM core (recurrence) =================
template<int T>
__device__ __forceinline__ void gemm_core(
    float (*As)[16][64], float (*Bs)[16][32], float (*Red)[32][32],
    const float* arow, const float* brow, int kg, int s)
{
    const int r = s >> 1, kofs = (s & 1) * 8;
    const int bk = s >> 2, bofs = (s & 3) * 8;
    const int mthr = s >> 3, nthr = s & 7;
    const int m0 = mthr * 4, n0 = nthr * 4;

    u64 acc[4][2];
#pragma unroll
    for (int i = 0; i < 4; i++) { acc[i][0] = 0ull; acc[i][1] = 0ull; }

    const float* aP = arow + kofs;
    const float* bP = brow + bk * 32 + bofs;

    float4 a0 = *(const float4*)aP;
    float4 a1 = *(const float4*)(aP + 4);
    float4 b0 = *(const float4*)bP;
    float4 b1 = *(const float4*)(bP + 4);

#pragma unroll 1
    for (int t = 0; t < T; t++) {
        {
            float va[8] = {a0.x, a0.y, a0.z, a0.w, a1.x, a1.y, a1.z, a1.w};
#pragma unroll
            for (int i = 0; i < 8; i++) {
                float2 d = make_float2(va[i], va[i]);
                *(float2*)&As[kg][kofs + i][2 * r] = d;
            }
            *(float4*)&Bs[kg][bk][bofs]     = b0;
            *(float4*)&Bs[kg][bk][bofs + 4] = b1;
        }
        __syncthreads();
        if (t + 1 < T) {
            aP += 16; bP += 512;
            a0 = *(const float4*)aP;
            a1 = *(const float4*)(aP + 4);
            b0 = *(const float4*)bP;
            b1 = *(const float4*)(bP + 4);
        }
#pragma unroll
        for (int k = 0; k < 16; k++) {
            float4 av0 = *(const float4*)&As[kg][k][2 * m0];
            float4 av1 = *(const float4*)&As[kg][k][2 * m0 + 4];
            float4 bv  = *(const float4*)&Bs[kg][k][n0];
            const u64* ap0 = (const u64*)&av0;
            const u64* ap1 = (const u64*)&av1;
            const u64* bp  = (const u64*)&bv;
            acc[0][0] = fma2(ap0[0], bp[0], acc[0][0]);
            acc[0][1] = fma2(ap0[0], bp[1], acc[0][1]);
            acc[1][0] = fma2(ap0[1], bp[0], acc[1][0]);
            acc[1][1] = fma2(ap0[1], bp[1], acc[1][1]);
            acc[2][0] = fma2(ap1[0], bp[0], acc[2][0]);
            acc[2][1] = fma2(ap1[0], bp[1], acc[2][1]);
            acc[3][0] = fma2(ap1[1], bp[0], acc[3][0]);
            acc[3][1] = fma2(ap1[1], bp[1], acc[3][1]);
        }
        __syncthreads();
    }
#pragma unroll
    for (int i = 0; i < 4; i++) {
        *(float2*)&Red[kg][m0 + i][n0]     = *(float2*)&acc[i][0];
        *(float2*)&Red[kg][m0 + i][n0 + 2] = *(float2*)&acc[i][1];
    }
    __syncthreads();
}

#define STEP_SMEM \
    __shared__ __align__(16) float As[4][16][64]; \
    __shared__ __align__(16) float Bs[4][16][32]; \
    __shared__ float Red[4][32][32];

// ---------------- prep: h0 (-> h,c), zc, rc ----------------
__global__ void __launch_bounds__(256) k_prep2(
    const float* __restrict__ Wl, const float* __restrict__ bl,
    const float* __restrict__ Wz, const float* __restrict__ bz,
    const float* __restrict__ Wr, const float* __restrict__ br)
{
    STEP_SMEM
    const int tid = threadIdx.x;
    const int kg = tid >> 6, s = tid & 63;
    const int mbase = blockIdx.x * 32;
    const int w = mbase + (s >> 1);
    const float* arow;
    if (w < 1024)      arow = Wl + (size_t)w * 512;
    else if (w < 2048) arow = Wz + (size_t)(w - 1024) * 1536;
    else               arow = Wr + (size_t)(w - 2048) * 1536;
    arow += kg * 128;
    const float* brow = g_weT + kg * 128 * 32;
    gemm_core<8>(As, Bs, Red, arow, brow, kg, s);

    const int m = tid >> 3, nq = (tid & 7) * 4;
    const int wo = mbase + m;
    float4 v0 = *(float4*)&Red[0][m][nq];
    float4 v1 = *(float4*)&Red[1][m][nq];
    float4 v2 = *(float4*)&Red[2][m][nq];
    float4 v3 = *(float4*)&Red[3][m][nq];
    float v[4] = { v0.x + v1.x + v2.x + v3.x, v0.y + v1.y + v2.y + v3.y,
                   v0.z + v1.z + v2.z + v3.z, v0.w + v1.w + v2.w + v3.w };
    if (wo < 1024) {
        float bb = bl[wo];
#pragma unroll
        for (int q = 0; q < 4; q++) {
            float h0 = v[q] + bb;
            g_hT[wo * 32 + nq + q] = h0;
            g_cT[wo * 32 + nq + q] = h0;
        }
    } else if (wo < 2048) {
        int i = wo - 1024; float bb = bz[i];
#pragma unroll
        for (int q = 0; q < 4; q++) g_zcT[i * 32 + nq + q] = v[q] + bb;
    } else {
        int e = wo - 2048; float bb = br[e];
#pragma unroll
        for (int q = 0; q < 4; q++) g_rcT[e * 32 + nq + q] = v[q] + bb;
    }
}

// ---------------- step phase 1: gates GEMM + LSTM pointwise ----------------
__global__ void __launch_bounds__(256) k_step1(const float* __restrict__ Whh, int t)
{
    STEP_SMEM
    const int tid = threadIdx.x;
    const int kg = tid >> 6, s = tid & 63;
    const int jbase = blockIdx.x * 8;
    const int r = s >> 1;
    const int wrow = ((r & 3) << 10) + jbase + (r >> 2);
    const float* arow = Whh + (size_t)wrow * 1024 + kg * 256;
    const float* brow = g_hT + kg * 256 * 32;
    gemm_core<16>(As, Bs, Red, arow, brow, kg, s);

    const int jloc = tid >> 5, b = tid & 31;
    const int j = jbase + jloc;
    float g4[4];
#pragma unroll
    for (int g = 0; g < 4; g++) {
        int m = jloc * 4 + g;
        g4[g] = Red[0][m][b] + Red[1][m][b] + Red[2][m][b] + Red[3][m][b];
    }
    const float* gx = g_gx + (size_t)(t * 32 + b) * 4096 + j;
    float gi = gx[0]    + g4[0];
    float gf = gx[1024] + g4[1];
    float gg = gx[2048] + g4[2];
    float go = gx[3072] + g4[3];
    float c  = g_cT[j * 32 + b];
    float cn = sigf(gf) * c + sigf(gi) * tanhf(gg);
    g_cT[j * 32 + b]  = cn;
    g_h1T[j * 32 + b] = sigf(go) * tanhf(cn);
}

// ---------------- step phase 2: z, t1, r*we ----------------
__global__ void __launch_bounds__(256) k_step2(
    const float* __restrict__ Wz, const float* __restrict__ Wh,
    const float* __restrict__ Wr)
{
    STEP_SMEM
    const int tid = threadIdx.x;
    const int kg = tid >> 6, s = tid & 63;
    const int mbase = blockIdx.x * 32;
    const int w = mbase + (s >> 1);
    const float* arow;
    if (w < 1024)      arow = Wz + (size_t)w * 1536 + 512;
    else if (w < 2048) arow = Wh + (size_t)(w - 1024) * 1536 + 512;
    else               arow = Wr + (size_t)(w - 2048) * 1536 + 512;
    arow += kg * 256;
    const float* brow = g_h1T + kg * 256 * 32;
    gemm_core<16>(As, Bs, Red, arow, brow, kg, s);

    const int m = tid >> 3, nq = (tid & 7) * 4;
    const int wo = mbase + m;
    float4 v0 = *(float4*)&Red[0][m][nq];
    float4 v1 = *(float4*)&Red[1][m][nq];
    float4 v2 = *(float4*)&Red[2][m][nq];
    float4 v3 = *(float4*)&Red[3][m][nq];
    float v[4] = { v0.x + v1.x + v2.x + v3.x, v0.y + v1.y + v2.y + v3.y,
                   v0.z + v1.z + v2.z + v3.z, v0.w + v1.w + v2.w + v3.w };
    if (wo < 1024) {
#pragma unroll
        for (int q = 0; q < 4; q++)
            g_zT[wo * 32 + nq + q] = sigf(g_zcT[wo * 32 + nq + q] + v[q]);
    } else if (wo < 2048) {
        int j = wo - 1024;
#pragma unroll
        for (int q = 0; q < 4; q++) g_t1T[j * 32 + nq + q] = v[q];
    } else {
        int e = wo - 2048;
#pragma unroll
        for (int q = 0; q < 4; q++) {
            float rr = sigf(g_rcT[e * 32 + nq + q] + v[q]);
            g_rwT[e * 32 + nq + q] = rr * g_weT[e * 32 + nq + q];
        }
    }
}

// ---------------- step phase 3: hh GEMM + h update ----------------
__global__ void __launch_bounds__(256) k_step3(
    const float* __restrict__ Wh, const float* __restrict__ bh, int t)
{
    STEP_SMEM
    const int tid = threadIdx.x;
    const int kg = tid >> 6, s = tid & 63;
    const int jbase = blockIdx.x * 32;
    const float* arow = Wh + (size_t)(jbase + (s >> 1)) * 1536 + kg * 128;
    const float* brow = g_rwT + kg * 128 * 32;
    gemm_core<8>(As, Bs, Red, arow, brow, kg, s);

    const int b = tid >> 3, jq = (tid & 7) * 4;
#pragma unroll
    for (int q = 0; q < 4; q++) {
        int m = jq + q, j = jbase + m;
        float v = Red[0][m][b] + Red[1][m][b] + Red[2][m][b] + Red[3][m][b];
        float hh = tanhf(g_t1T[j * 32 + b] + v + bh[j]);
        float z  = g_zT[j * 32 + b];
        float h1 = g_h1T[j * 32 + b];
        float hn = (1.f - z) * h1 + z * hh;
        g_hT[j * 32 + b] = hn;
        g_hs[(size_t)(t * 32 + b) * 1024 + j] = hn;
    }
}

// ---------------- tail: hf, cf into output ----------------
__global__ void k_tail(float* __restrict__ out)
{
    int idx = blockIdx.x * blockDim.x + threadIdx.x;   // < 32768
    int b = idx >> 10, j = idx & 1023;
    out[32768000 + idx]         = g_hT[j * 32 + b];
    out[32768000 + 32768 + idx] = g_cT[j * 32 + b];
}

// ---------------- launch ----------------
extern "C" void kernel_launch(void* const* d_in, const int* in_sizes, int n_in,
                              void* d_out, int out_size)
{
    const int*   word = (const int*)d_in[0];
    const int*   seq  = (const int*)d_in[1];
    const float* emb  = (const float*)d_in[2];
    const float* Wl   = (const float*)d_in[3];
    const float* bl   = (const float*)d_in[4];
    const float* Wih  = (const float*)d_in[5];
    const float* Whh  = (const float*)d_in[6];
    const float* bih  = (const float*)d_in[7];
    const float* bhh  = (const float*)d_in[8];
    const float* Wz   = (const float*)d_in[9];
    const float* bz   = (const float*)d_in[10];
    const float* Wr   = (const float*)d_in[11];
    const float* br   = (const float*)d_in[12];
    const float* Wh   = (const float*)d_in[13];
    const float* bh   = (const float*)d_in[14];
    const float* Wo   = (const float*)d_in[15];
    const float* bo   = (const float*)d_in[16];
    float* out = (float*)d_out;

    void *p_se, *p_gx, *p_bsum, *p_hs;
    cudaGetSymbolAddress(&p_se, g_se);
    cudaGetSymbolAddress(&p_gx, g_gx);
    cudaGetSymbolAddress(&p_bsum, g_bsum);
    cudaGetSymbolAddress(&p_hs, g_hs);

    cudaFuncSetAttribute(gemm_mma, cudaFuncAttributeMaxDynamicSharedMemorySize, GM_SMEM);

    k_gather<<<2048, 256>>>(word, seq, emb, bih, bhh);
    k_prep2<<<80, 256>>>(Wl, bl, Wz, bz, Wr, br);

    // gx = se @ Wih.T + (bih+bhh):  M=1024, N=4096, K=512  (HMMA split-bf16)
    gemm_mma<<<dim3(8, 32), 256, GM_SMEM>>>((const float*)p_se, Wih,
                                            (const float*)p_bsum, (float*)p_gx,
                                            512, 4096);

    for (int t = 0; t < 32; t++) {
        k_step1<<<128, 256>>>(Whh, t);
        k_step2<<<80, 256>>>(Wz, Wh, Wr);
        k_step3<<<32, 256>>>(Wh, bh, t);
    }

    // logits = hs @ Wo.T + bo:  M=1024, N=32000, K=1024  (HMMA split-bf16)
    gemm_mma<<<dim3(8, 250), 256, GM_SMEM>>>((const float*)p_hs, Wo, bo, out,
                                             1024, 32000);

    k_tail<<<128, 256>>>(out);
}

// round 13
// speedup vs baseline: 4.2877x; 1.4566x over previous
#include <cuda_runtime.h>
#include <cuda_bf16.h>
#include <math.h>
#include <stdint.h>

typedef unsigned long long u64;

// ---------------- scratch (device globals; no allocs allowed) ----------------
__device__ float g_weT[512 * 32];        // we transposed [e][b]
__device__ float g_se[1024 * 512];       // se [(t*32+b)][e]
__device__ float g_bsum[4096];           // bih + bhh
__device__ float g_gx[1024 * 4096];      // se @ Wih.T + bsum   [(t*32+b)][4H]
__device__ float g_hT[1024 * 32];        // h  [j][b]
__device__ float g_cT[1024 * 32];        // c  [j][b]
__device__ float g_h1T[1024 * 32];       // post-LSTM h [j][b]
__device__ float g_zcT[1024 * 32];       // we-part of z preact [j][b]
__device__ float g_rcT[512 * 32];        // we-part of r preact [e][b]
__device__ float g_zT[1024 * 32];        // z [j][b]
__device__ float g_t1T[1024 * 32];       // h1 @ Wh_h.T [j][b]
__device__ float g_hs[1024 * 1024];      // hs [(t*32+b)][j]  (GEMM A)

// ---------------- fragment-layout weights (hi/lo split bf16) ----------------
// Per 16x16 tile per lane: uint4 hi {a0,a1,a2,a3}, uint4 lo. Index: (tile*32+lane)*2.
__device__ uint4 g_WhhF[256 * 64 * 32 * 2];   // gates: 256 row-tiles (gate-paired) x 64 kt
__device__ uint4 g_WzrF[160 * 64 * 32 * 2];   // z(64) | t1(64) | r(32) row-tiles x 64 kt
__device__ uint4 g_WheF[64 * 32 * 32 * 2];    // hh: 64 row-tiles x 32 kt (K=512)
// ---------------- fragment-layout state (B-frags) ----------------
// Per k16n8 tile per lane: uint4 {hi_b0, hi_b1, lo_b0, lo_b1}. Index: (kt*4+nt)*32+lane.
__device__ uint4 g_hF[64 * 4 * 32];
__device__ uint4 g_h1F[64 * 4 * 32];
__device__ uint4 g_rwF[32 * 4 * 32];

__device__ __forceinline__ float sigf(float x) { return 1.f / (1.f + expf(-x)); }

__device__ __forceinline__ u64 fma2(u64 a, u64 b, u64 c) {
    u64 d;
    asm("fma.rn.f32x2 %0, %1, %2, %3;" : "=l"(d) : "l"(a), "l"(b), "l"(c));
    return d;
}

__device__ __forceinline__ uint32_t smem_u32(const void* p) {
    uint32_t a;
    asm("{ .reg .u64 t; cvta.to.shared.u64 t, %1; cvt.u32.u64 %0, t; }" : "=r"(a) : "l"(p));
    return a;
}

// ================= mma.sync helpers (base-target PTX, HMMA) =================
__device__ __forceinline__ void ldsm_x4(uint32_t& r0, uint32_t& r1, uint32_t& r2, uint32_t& r3,
                                        uint32_t addr) {
    asm volatile("ldmatrix.sync.aligned.m8n8.x4.shared.b16 {%0,%1,%2,%3}, [%4];"
        : "=r"(r0), "=r"(r1), "=r"(r2), "=r"(r3) : "r"(addr));
}
__device__ __forceinline__ void mma16816(float* c, const uint32_t* a, const uint32_t* b) {
    asm volatile("mma.sync.aligned.m16n8k16.row.col.f32.bf16.bf16.f32 "
        "{%0,%1,%2,%3}, {%4,%5,%6,%7}, {%8,%9}, {%0,%1,%2,%3};"
        : "+f"(c[0]), "+f"(c[1]), "+f"(c[2]), "+f"(c[3])
        : "r"(a[0]), "r"(a[1]), "r"(a[2]), "r"(a[3]), "r"(b[0]), "r"(b[1]));
}

__device__ __forceinline__ uint32_t pack_bf16(float a, float b) {
    uint32_t lo = __bfloat16_as_ushort(__float2bfloat16_rn(a));
    uint32_t hi = __bfloat16_as_ushort(__float2bfloat16_rn(b));
    return lo | (hi << 16);
}
__device__ __forceinline__ void cvt_split(float4 v, uint2& hh, uint2& ll) {
    float hx = __bfloat162float(__float2bfloat16_rn(v.x));
    float hy = __bfloat162float(__float2bfloat16_rn(v.y));
    float hz = __bfloat162float(__float2bfloat16_rn(v.z));
    float hw = __bfloat162float(__float2bfloat16_rn(v.w));
    hh = make_uint2(pack_bf16(v.x, v.y), pack_bf16(v.z, v.w));
    ll = make_uint2(pack_bf16(v.x - hx, v.y - hy), pack_bf16(v.z - hz, v.w - hw));
}
__device__ __forceinline__ void split2(float a, float b, uint32_t& h, uint32_t& l) {
    float ah = __bfloat162float(__float2bfloat16_rn(a));
    float bh = __bfloat162float(__float2bfloat16_rn(b));
    h = pack_bf16(a, b);
    l = pack_bf16(a - ah, b - bh);
}

// ======= split-bf16 mma.sync GEMM: C[M,N] = A[M,K] @ B[N,K]^T + bias[N] =======
#define MAT_B   10240            // 128 * 40 * 2 bytes
#define BUF_B   (4 * MAT_B)      // Ahi | Alo | Bhi | Blo
#define GM_SMEM (2 * BUF_B)      // double buffered

__global__ void __launch_bounds__(256) gemm_mma(
    const float* __restrict__ A, const float* __restrict__ B,
    const float* __restrict__ bias, float* __restrict__ C,
    int K, int N)
{
    extern __shared__ char smem[];
    const uint32_t sb = smem_u32(smem);
    const int tid = threadIdx.x;
    const int wid = tid >> 5, lane = tid & 31;
    const int wm = wid >> 1, wn = wid & 1;
    const int mBase = blockIdx.x * 128;
    const int nBase = blockIdx.y * 128;
    const int NC = K >> 5;

    float acc[2][8][4];
#pragma unroll
    for (int mt = 0; mt < 2; mt++)
#pragma unroll
        for (int nt = 0; nt < 8; nt++)
#pragma unroll
            for (int q = 0; q < 4; q++) acc[mt][nt][q] = 0.f;

    int lrow[4], lq[4];
#pragma unroll
    for (int i = 0; i < 4; i++) {
        int idx = tid * 4 + i;
        lrow[i] = idx >> 3;
        lq[i] = idx & 7;
    }

    float4 ra[4], rb[4];
#pragma unroll
    for (int i = 0; i < 4; i++) {
        ra[i] = *(const float4*)(A + (size_t)(mBase + lrow[i]) * K + lq[i] * 4);
        rb[i] = *(const float4*)(B + (size_t)(nBase + lrow[i]) * K + lq[i] * 4);
    }
#pragma unroll
    for (int i = 0; i < 4; i++) {
        uint2 hh, ll;
        uint32_t off = (uint32_t)(lrow[i] * 80 + lq[i] * 8);
        cvt_split(ra[i], hh, ll);
        *(uint2*)(smem + off) = hh;
        *(uint2*)(smem + MAT_B + off) = ll;
        cvt_split(rb[i], hh, ll);
        *(uint2*)(smem + 2 * MAT_B + off) = hh;
        *(uint2*)(smem + 3 * MAT_B + off) = ll;
    }
    __syncthreads();

    const uint32_t a_ls = (uint32_t)(wm * 32 + (lane & 15)) * 80 + (lane >> 4) * 16;
    const uint32_t b_ls = (uint32_t)(wn * 64 + (lane & 15)) * 80 + (lane >> 4) * 16;

    for (int c = 0; c < NC; c++) {
        const int p = c & 1;
        const uint32_t bufb = sb + p * BUF_B;

        if (c + 1 < NC) {
            const int kc = (c + 1) * 32;
#pragma unroll
            for (int i = 0; i < 4; i++) {
                ra[i] = *(const float4*)(A + (size_t)(mBase + lrow[i]) * K + kc + lq[i] * 4);
                rb[i] = *(const float4*)(B + (size_t)(nBase + lrow[i]) * K + kc + lq[i] * 4);
            }
        }

#pragma unroll
        for (int ks = 0; ks < 2; ks++) {
            uint32_t ahi[2][4], alo[2][4];
#pragma unroll
            for (int mt = 0; mt < 2; mt++) {
                uint32_t off = a_ls + mt * 16 * 80 + ks * 32;
                ldsm_x4(ahi[mt][0], ahi[mt][1], ahi[mt][2], ahi[mt][3], bufb + off);
                ldsm_x4(alo[mt][0], alo[mt][1], alo[mt][2], alo[mt][3], bufb + MAT_B + off);
            }
            uint32_t bhi[8][2], blo[8][2];
#pragma unroll
            for (int g = 0; g < 4; g++) {
                uint32_t off = b_ls + g * 16 * 80 + ks * 32;
                uint32_t r0, r1, r2, r3;
                ldsm_x4(r0, r1, r2, r3, bufb + 2 * MAT_B + off);
                bhi[2 * g][0] = r0; bhi[2 * g][1] = r2;
                bhi[2 * g + 1][0] = r1; bhi[2 * g + 1][1] = r3;
                ldsm_x4(r0, r1, r2, r3, bufb + 3 * MAT_B + off);
                blo[2 * g][0] = r0; blo[2 * g][1] = r2;
                blo[2 * g + 1][0] = r1; blo[2 * g + 1][1] = r3;
            }
#pragma unroll
            for (int mt = 0; mt < 2; mt++)
#pragma unroll
                for (int nt = 0; nt < 8; nt++) {
                    mma16816(acc[mt][nt], ahi[mt], bhi[nt]);
                    mma16816(acc[mt][nt], ahi[mt], blo[nt]);
                    mma16816(acc[mt][nt], alo[mt], bhi[nt]);
                }
        }

        if (c + 1 < NC) {
            char* dst = smem + (p ^ 1) * BUF_B;
#pragma unroll
            for (int i = 0; i < 4; i++) {
                uint2 hh, ll;
                uint32_t off = (uint32_t)(lrow[i] * 80 + lq[i] * 8);
                cvt_split(ra[i], hh, ll);
                *(uint2*)(dst + off) = hh;
                *(uint2*)(dst + MAT_B + off) = ll;
                cvt_split(rb[i], hh, ll);
                *(uint2*)(dst + 2 * MAT_B + off) = hh;
                *(uint2*)(dst + 3 * MAT_B + off) = ll;
            }
        }
        __syncthreads();
    }

#pragma unroll
    for (int mt = 0; mt < 2; mt++) {
        const int row0 = mBase + wm * 32 + mt * 16 + (lane >> 2);
#pragma unroll
        for (int nt = 0; nt < 8; nt++) {
            const int col = nBase + wn * 64 + nt * 8 + (lane & 3) * 2;
            float2 bv = *(const float2*)(bias + col);
            float2 o0 = make_float2(acc[mt][nt][0] + bv.x, acc[mt][nt][1] + bv.y);
            float2 o1 = make_float2(acc[mt][nt][2] + bv.x, acc[mt][nt][3] + bv.y);
            *(float2*)(C + (size_t)row0 * N + col) = o0;
            *(float2*)(C + (size_t)(row0 + 8) * N + col) = o1;
        }
    }
}

// ---------------- weight fragment conversion (runs once) ----------------
__global__ void __launch_bounds__(256) k_convW(
    const float* __restrict__ Whh, const float* __restrict__ Wz,
    const float* __restrict__ Wh, const float* __restrict__ Wr)
{
    int g = blockIdx.x * 256 + threadIdx.x;
    if (g >= 28672 * 32) return;
    const int tile = g >> 5, lane = g & 31;
    const int rl = lane >> 2;                 // 0..7
    const int kq = (lane & 3) * 2;            // 0,2,4,6
    const float *r0p, *r8p;
    uint4* dst;
    if (tile < 16384) {                       // Whh (gates)
        int rt = tile >> 6, kt = tile & 63;
        int j0 = (rt >> 1) * 8;
        int gate_lo = (rt & 1) * 2;
        int k0 = kt * 16 + kq;
        r0p = Whh + (size_t)(gate_lo * 1024 + j0 + rl) * 1024 + k0;
        r8p = Whh + (size_t)((gate_lo + 1) * 1024 + j0 + rl) * 1024 + k0;
        dst = g_WhhF + ((size_t)tile * 32 + lane) * 2;
    } else if (tile < 26624) {                // zrt (h-part, col offset 512)
        int t2 = tile - 16384;
        int rt = t2 >> 6, kt = t2 & 63;
        int k0 = kt * 16 + kq;
        const float* base;
        int row;
        if (rt < 64)      { base = Wz; row = rt * 16; }
        else if (rt < 128){ base = Wh; row = (rt - 64) * 16; }
        else              { base = Wr; row = (rt - 128) * 16; }
        r0p = base + (size_t)(row + rl) * 1536 + 512 + k0;
        r8p = base + (size_t)(row + rl + 8) * 1536 + 512 + k0;
        dst = g_WzrF + ((size_t)t2 * 32 + lane) * 2;
    } else {                                  // hh (Wh e-part, K=512)
        int t3 = tile - 26624;
        int rt = t3 >> 5, kt = t3 & 31;
        int k0 = kt * 16 + kq;
        r0p = Wh + (size_t)(rt * 16 + rl) * 1536 + k0;
        r8p = Wh + (size_t)(rt * 16 + rl + 8) * 1536 + k0;
        dst = g_WheF + ((size_t)t3 * 32 + lane) * 2;
    }
    uint4 hi, lo;
    split2(r0p[0], r0p[1], hi.x, lo.x);
    split2(r8p[0], r8p[1], hi.y, lo.y);
    split2(r0p[8], r0p[9], hi.z, lo.z);
    split2(r8p[8], r8p[9], hi.w, lo.w);
    dst[0] = hi;
    dst[1] = lo;
}

// ---------------- shared step-MMA slice (no smem operands) ----------------
__device__ __forceinline__ void step_mma_slice(
    const uint4* __restrict__ Af, const uint4* __restrict__ Bf,
    int rt, int ktTot, int kt0, int ktN, int lane, float acc[4][4])
{
#pragma unroll 2
    for (int kt = kt0; kt < kt0 + ktN; kt++) {
        const uint4* ap = Af + (((size_t)rt * ktTot + kt) * 32 + lane) * 2;
        uint4 ahi = ap[0];
        uint4 alo = ap[1];
        const uint4* bp = Bf + (size_t)(kt * 4) * 32 + lane;
        uint4 bv0 = bp[0], bv1 = bp[32], bv2 = bp[64], bv3 = bp[96];
        uint4 bvs[4] = {bv0, bv1, bv2, bv3};
#pragma unroll
        for (int nt = 0; nt < 4; nt++) {
            uint32_t bh2[2] = {bvs[nt].x, bvs[nt].y};
            uint32_t bl2[2] = {bvs[nt].z, bvs[nt].w};
            mma16816(acc[nt], (const uint32_t*)&ahi, bh2);
            mma16816(acc[nt], (const uint32_t*)&ahi, bl2);
            mma16816(acc[nt], (const uint32_t*)&alo, bh2);
        }
    }
}

__device__ __forceinline__ void store_cfrag(float S[8][16][33], int wid, int lane,
                                            float acc[4][4])
{
    int r = lane >> 2, c0 = (lane & 3) * 2;
#pragma unroll
    for (int nt = 0; nt < 4; nt++) {
        S[wid][r][nt * 8 + c0]     = acc[nt][0];
        S[wid][r][nt * 8 + c0 + 1] = acc[nt][1];
        S[wid][r + 8][nt * 8 + c0]     = acc[nt][2];
        S[wid][r + 8][nt * 8 + c0 + 1] = acc[nt][3];
    }
}

// ---------------- step 1: gates MMA + LSTM pointwise ----------------
__global__ void __launch_bounds__(256) gates_mma(int t)
{
    __shared__ float S[8][16][33];
    const int tid = threadIdx.x, lane = tid & 31, wid = tid >> 5;
    const int bid = blockIdx.x;
    const int mt = wid & 1, ks = wid >> 1;
    float acc[4][4] = {};
    step_mma_slice(g_WhhF, g_hF, bid * 2 + mt, 64, ks * 16, 16, lane, acc);
    store_cfrag(S, wid, lane, acc);
    __syncthreads();

    const int jl = tid >> 5, b = tid & 31;
    const int j = bid * 8 + jl;
    float gi = 0, gf = 0, gg = 0, go = 0;
#pragma unroll
    for (int k = 0; k < 4; k++) {
        gi += S[k * 2][jl][b];     gf += S[k * 2][jl + 8][b];
        gg += S[k * 2 + 1][jl][b]; go += S[k * 2 + 1][jl + 8][b];
    }
    const float* gx = g_gx + (size_t)(t * 32 + b) * 4096 + j;
    gi += gx[0]; gf += gx[1024]; gg += gx[2048]; go += gx[3072];
    float c = g_cT[j * 32 + b];
    float cn = sigf(gf) * c + sigf(gi) * tanhf(gg);
    g_cT[j * 32 + b] = cn;
    float h1 = sigf(go) * tanhf(cn);
    g_h1T[j * 32 + b] = h1;
    __syncthreads();
    S[0][jl][b] = h1;           // stage 8 rows x 32 b
    __syncthreads();
    if (tid < 128) {            // write half-tile B-frags for h1
        int nt = tid >> 5, l = tid & 31;
        int k0l = (l & 3) * 2, n = nt * 8 + (l >> 2);
        uint32_t hh_, ll_;
        split2(S[0][k0l][n], S[0][k0l + 1][n], hh_, ll_);
        int kt = bid >> 1, half = bid & 1;
        uint32_t* d = (uint32_t*)&g_h1F[(kt * 4 + nt) * 32 + l];
        d[half] = hh_;
        d[2 + half] = ll_;
    }
}

// ---------------- step 2: z / t1 / r*we MMA ----------------
__global__ void __launch_bounds__(256) zrt_mma()
{
    __shared__ float S[8][16][33];
    const int tid = threadIdx.x, lane = tid & 31, wid = tid >> 5;
    const int bid = blockIdx.x;
    const int mt = wid & 1, ks = wid >> 1;
    float acc[4][4] = {};
    step_mma_slice(g_WzrF, g_h1F, bid * 2 + mt, 64, ks * 16, 16, lane, acc);
    store_cfrag(S, wid, lane, acc);
    __syncthreads();

    const int m = tid >> 3, nq = (tid & 7) * 4;
    float v[4];
#pragma unroll
    for (int q = 0; q < 4; q++) {
        float s = 0;
#pragma unroll
        for (int k = 0; k < 4; k++) s += S[(k << 1) | (m >> 4)][m & 15][nq + q];
        v[q] = s;
    }
    if (bid < 32) {
        int j = bid * 32 + m;
#pragma unroll
        for (int q = 0; q < 4; q++)
            g_zT[j * 32 + nq + q] = sigf(g_zcT[j * 32 + nq + q] + v[q]);
    } else if (bid < 64) {
        int j = (bid - 32) * 32 + m;
#pragma unroll
        for (int q = 0; q < 4; q++) g_t1T[j * 32 + nq + q] = v[q];
    } else {
        int e = (bid - 64) * 32 + m;
        float rw[4];
#pragma unroll
        for (int q = 0; q < 4; q++)
            rw[q] = sigf(g_rcT[e * 32 + nq + q] + v[q]) * g_weT[e * 32 + nq + q];
        __syncthreads();
        float (*S2)[33] = (float(*)[33])S;
#pragma unroll
        for (int q = 0; q < 4; q++) S2[m][nq + q] = rw[q];
        __syncthreads();
        int ktl = tid >> 7, nt = (tid >> 5) & 3, l = tid & 31;
        int k0l = ktl * 16 + (l & 3) * 2, n = nt * 8 + (l >> 2);
        uint32_t h0, l0, h1, l1;
        split2(S2[k0l][n],     S2[k0l + 1][n], h0, l0);
        split2(S2[k0l + 8][n], S2[k0l + 9][n], h1, l1);
        int kt = (bid - 64) * 2 + ktl;
        g_rwF[(kt * 4 + nt) * 32 + l] = make_uint4(h0, h1, l0, l1);
    }
}

// ---------------- step 3: hh MMA + h update ----------------
__global__ void __launch_bounds__(256) hh_mma(const float* __restrict__ bh, int t)
{
    __shared__ float S[8][16][33];
    const int tid = threadIdx.x, lane = tid & 31, wid = tid >> 5;
    const int bid = blockIdx.x;
    const int mt = wid & 1, ks = wid >> 1;
    float acc[4][4] = {};
    step_mma_slice(g_WheF, g_rwF, bid * 2 + mt, 32, ks * 8, 8, lane, acc);
    store_cfrag(S, wid, lane, acc);
    __syncthreads();

    const int m = tid >> 3, nq = (tid & 7) * 4;
    float v[4];
#pragma unroll
    for (int q = 0; q < 4; q++) {
        float s = 0;
#pragma unroll
        for (int k = 0; k < 4; k++) s += S[(k << 1) | (m >> 4)][m & 15][nq + q];
        v[q] = s;
    }
    const int j = bid * 32 + m;
    const float bhv = bh[j];
    float hn[4];
#pragma unroll
    for (int q = 0; q < 4; q++) {
        int b = nq + q;
        float hh = tanhf(g_t1T[j * 32 + b] + v[q] + bhv);
        float z = g_zT[j * 32 + b];
        float h1 = g_h1T[j * 32 + b];
        hn[q] = (1.f - z) * h1 + z * hh;
        g_hT[j * 32 + b] = hn[q];
        g_hs[(size_t)(t * 32 + b) * 1024 + j] = hn[q];
    }
    __syncthreads();
    float (*S2)[33] = (float(*)[33])S;
#pragma unroll
    for (int q = 0; q < 4; q++) S2[m][nq + q] = hn[q];
    __syncthreads();
    int ktl = tid >> 7, nt = (tid >> 5) & 3, l = tid & 31;
    int k0l = ktl * 16 + (l & 3) * 2, n = nt * 8 + (l >> 2);
    uint32_t h0, l0, h1, l1;
    split2(S2[k0l][n],     S2[k0l + 1][n], h0, l0);
    split2(S2[k0l + 8][n], S2[k0l + 9][n], h1, l1);
    int kt = bid * 2 + ktl;
    g_hF[(kt * 4 + nt) * 32 + l] = make_uint4(h0, h1, l0, l1);
}

// ---------------- gather: we (transposed), se, bias sum ----------------
__global__ void k_gather(const int* __restrict__ word, const int* __restrict__ seq,
                         const float* __restrict__ emb,
                         const float* __restrict__ bih, const float* __restrict__ bhh)
{
    int idx = blockIdx.x * blockDim.x + threadIdx.x;
    if (idx < 1024 * 512) {
        int m = idx >> 9, e = idx & 511;
        g_se[idx] = emb[(size_t)seq[m] * 512 + e];
    }
    if (idx < 512 * 32) {
        int e = idx >> 5, b = idx & 31;
        g_weT[idx] = emb[(size_t)word[b] * 512 + e];
    }
    if (idx < 4096) g_bsum[idx] = bih[idx] + bhh[idx];
}

// ================= fp32 micro-GEMM core (prep only) =================
template<int T>
__device__ __forceinline__ void gemm_core(
    float (*As)[16][64], float (*Bs)[16][32], float (*Red)[32][32],
    const float* arow, const float* brow, int kg, int s)
{
    const int r = s >> 1, kofs = (s & 1) * 8;
    const int bk = s >> 2, bofs = (s & 3) * 8;
    const int mthr = s >> 3, nthr = s & 7;
    const int m0 = mthr * 4, n0 = nthr * 4;

    u64 acc[4][2];
#pragma unroll
    for (int i = 0; i < 4; i++) { acc[i][0] = 0ull; acc[i][1] = 0ull; }

    const float* aP = arow + kofs;
    const float* bP = brow + bk * 32 + bofs;

    float4 a0 = *(const float4*)aP;
    float4 a1 = *(const float4*)(aP + 4);
    float4 b0 = *(const float4*)bP;
    float4 b1 = *(const float4*)(bP + 4);

#pragma unroll 1
    for (int t = 0; t < T; t++) {
        {
            float va[8] = {a0.x, a0.y, a0.z, a0.w, a1.x, a1.y, a1.z, a1.w};
#pragma unroll
            for (int i = 0; i < 8; i++) {
                float2 d = make_float2(va[i], va[i]);
                *(float2*)&As[kg][kofs + i][2 * r] = d;
            }
            *(float4*)&Bs[kg][bk][bofs]     = b0;
            *(float4*)&Bs[kg][bk][bofs + 4] = b1;
        }
        __syncthreads();
        if (t + 1 < T) {
            aP += 16; bP += 512;
            a0 = *(const float4*)aP;
            a1 = *(const float4*)(aP + 4);
            b0 = *(const float4*)bP;
            b1 = *(const float4*)(bP + 4);
        }
#pragma unroll
        for (int k = 0; k < 16; k++) {
            float4 av0 = *(const float4*)&As[kg][k][2 * m0];
            float4 av1 = *(const float4*)&As[kg][k][2 * m0 + 4];
            float4 bv  = *(const float4*)&Bs[kg][k][n0];
            const u64* ap0 = (const u64*)&av0;
            const u64* ap1 = (const u64*)&av1;
            const u64* bp  = (const u64*)&bv;
            acc[0][0] = fma2(ap0[0], bp[0], acc[0][0]);
            acc[0][1] = fma2(ap0[0], bp[1], acc[0][1]);
            acc[1][0] = fma2(ap0[1], bp[0], acc[1][0]);
            acc[1][1] = fma2(ap0[1], bp[1], acc[1][1]);
            acc[2][0] = fma2(ap1[0], bp[0], acc[2][0]);
            acc[2][1] = fma2(ap1[0], bp[1], acc[2][1]);
            acc[3][0] = fma2(ap1[1], bp[0], acc[3][0]);
            acc[3][1] = fma2(ap1[1], bp[1], acc[3][1]);
        }
        __syncthreads();
    }
#pragma unroll
    for (int i = 0; i < 4; i++) {
        *(float2*)&Red[kg][m0 + i][n0]     = *(float2*)&acc[i][0];
        *(float2*)&Red[kg][m0 + i][n0 + 2] = *(float2*)&acc[i][1];
    }
    __syncthreads();
}

// ---------------- prep: h0 (-> h,c,hF), zc, rc ----------------
__global__ void __launch_bounds__(256) k_prep2(
    const float* __restrict__ Wl, const float* __restrict__ bl,
    const float* __restrict__ Wz, const float* __restrict__ bz,
    const float* __restrict__ Wr, const float* __restrict__ br)
{
    __shared__ __align__(16) float As[4][16][64];
    __shared__ __align__(16) float Bs[4][16][32];
    __shared__ float Red[4][32][32];
    const int tid = threadIdx.x;
    const int kg = tid >> 6, s = tid & 63;
    const int mbase = blockIdx.x * 32;
    const int w = mbase + (s >> 1);
    const float* arow;
    if (w < 1024)      arow = Wl + (size_t)w * 512;
    else if (w < 2048) arow = Wz + (size_t)(w - 1024) * 1536;
    else               arow = Wr + (size_t)(w - 2048) * 1536;
    arow += kg * 128;
    const float* brow = g_weT + kg * 128 * 32;
    gemm_core<8>(As, Bs, Red, arow, brow, kg, s);

    const int m = tid >> 3, nq = (tid & 7) * 4;
    const int wo = mbase + m;
    float4 v0 = *(float4*)&Red[0][m][nq];
    float4 v1 = *(float4*)&Red[1][m][nq];
    float4 v2 = *(float4*)&Red[2][m][nq];
    float4 v3 = *(float4*)&Red[3][m][nq];
    float v[4] = { v0.x + v1.x + v2.x + v3.x, v0.y + v1.y + v2.y + v3.y,
                   v0.z + v1.z + v2.z + v3.z, v0.w + v1.w + v2.w + v3.w };
    if (wo < 1024) {
        float bb = bl[wo];
        float h0v[4];
#pragma unroll
        for (int q = 0; q < 4; q++) {
            h0v[q] = v[q] + bb;
            g_hT[wo * 32 + nq + q] = h0v[q];
            g_cT[wo * 32 + nq + q] = h0v[q];
        }
        // h-frag write (full 2 k-tiles per block)
        __syncthreads();
        float (*S2)[33] = (float(*)[33])&As[0][0][0];
#pragma unroll
        for (int q = 0; q < 4; q++) S2[m][nq + q] = h0v[q];
        __syncthreads();
        int ktl = tid >> 7, nt = (tid >> 5) & 3, l = tid & 31;
        int k0l = ktl * 16 + (l & 3) * 2, n = nt * 8 + (l >> 2);
        uint32_t h0, l0, h1, l1;
        split2(S2[k0l][n],     S2[k0l + 1][n], h0, l0);
        split2(S2[k0l + 8][n], S2[k0l + 9][n], h1, l1);
        int kt = blockIdx.x * 2 + ktl;
        g_hF[(kt * 4 + nt) * 32 + l] = make_uint4(h0, h1, l0, l1);
    } else if (wo < 2048) {
        int i = wo - 1024; float bb = bz[i];
#pragma unroll
        for (int q = 0; q < 4; q++) g_zcT[i * 32 + nq + q] = v[q] + bb;
    } else {
        int e = wo - 2048; float bb = br[e];
#pragma unroll
        for (int q = 0; q < 4; q++) g_rcT[e * 32 + nq + q] = v[q] + bb;
    }
}

// ---------------- tail: hf, cf into output ----------------
__global__ void k_tail(float* __restrict__ out)
{
    int idx = blockIdx.x * blockDim.x + threadIdx.x;   // < 32768
    int b = idx >> 10, j = idx & 1023;
    out[32768000 + idx]         = g_hT[j * 32 + b];
    out[32768000 + 32768 + idx] = g_cT[j * 32 + b];
}

// ---------------- launch ----------------
extern "C" void kernel_launch(void* const* d_in, const int* in_sizes, int n_in,
                              void* d_out, int out_size)
{
    const int*   word = (const int*)d_in[0];
    const int*   seq  = (const int*)d_in[1];
    const float* emb  = (const float*)d_in[2];
    const float* Wl   = (const float*)d_in[3];
    const float* bl   = (const float*)d_in[4];
    const float* Wih  = (const float*)d_in[5];
    const float* Whh  = (const float*)d_in[6];
    const float* bih  = (const float*)d_in[7];
    const float* bhh  = (const float*)d_in[8];
    const float* Wz   = (const float*)d_in[9];
    const float* bz   = (const float*)d_in[10];
    const float* Wr   = (const float*)d_in[11];
    const float* br   = (const float*)d_in[12];
    const float* Wh   = (const float*)d_in[13];
    const float* bh   = (const float*)d_in[14];
    const float* Wo   = (const float*)d_in[15];
    const float* bo   = (const float*)d_in[16];
    float* out = (float*)d_out;

    void *p_se, *p_gx, *p_bsum, *p_hs;
    cudaGetSymbolAddress(&p_se, g_se);
    cudaGetSymbolAddress(&p_gx, g_gx);
    cudaGetSymbolAddress(&p_bsum, g_bsum);
    cudaGetSymbolAddress(&p_hs, g_hs);

    cudaFuncSetAttribute(gemm_mma, cudaFuncAttributeMaxDynamicSharedMemorySize, GM_SMEM);

    k_convW<<<3584, 256>>>(Whh, Wz, Wh, Wr);
    k_gather<<<2048, 256>>>(word, seq, emb, bih, bhh);
    k_prep2<<<80, 256>>>(Wl, bl, Wz, bz, Wr, br);

    // gx = se @ Wih.T + (bih+bhh):  M=1024, N=4096, K=512  (HMMA split-bf16)
    gemm_mma<<<dim3(8, 32), 256, GM_SMEM>>>((const float*)p_se, Wih,
                                            (const float*)p_bsum, (float*)p_gx,
                                            512, 4096);

    for (int t = 0; t < 32; t++) {
        gates_mma<<<128, 256>>>(t);
        zrt_mma<<<80, 256>>>();
        hh_mma<<<32, 256>>>(bh, t);
    }

    // logits = hs @ Wo.T + bo:  M=1024, N=32000, K=1024  (HMMA split-bf16)
    gemm_mma<<<dim3(8, 250), 256, GM_SMEM>>>((const float*)p_hs, Wo, bo, out,
                                             1024, 32000);

    k_tail<<<128, 256>>>(out);
}

// round 14
// speedup vs baseline: 4.6628x; 1.0875x over previous
#include <cuda_runtime.h>
#include <cuda_bf16.h>
#include <math.h>
#include <stdint.h>

typedef unsigned long long u64;

// ---------------- scratch (device globals; no allocs allowed) ----------------
__device__ float g_weT[512 * 32];        // we transposed [e][b]
__device__ float g_se[1024 * 512];       // se [(t*32+b)][e]
__device__ float g_bsum[4096];           // bih + bhh
__device__ float g_gx[1024 * 4096];      // se @ Wih.T + bsum   [(t*32+b)][4H]
__device__ float g_hT[1024 * 32];        // h  [j][b]
__device__ float g_cT[1024 * 32];        // c  [j][b]
__device__ float g_h1T[1024 * 32];       // post-LSTM h [j][b]
__device__ float g_zcT[1024 * 32];       // we-part of z preact [j][b]
__device__ float g_rcT[512 * 32];        // we-part of r preact [e][b]
__device__ float g_zT[1024 * 32];        // z [j][b]
__device__ float g_t1T[1024 * 32];       // h1 @ Wh_h.T [j][b]

// ---------------- fragment-layout weights (hi/lo split bf16) ----------------
__device__ uint4 g_WhhF[256 * 64 * 32 * 2];   // gates: 256 row-tiles (gate-paired) x 64 kt
__device__ uint4 g_WzrF[160 * 64 * 32 * 2];   // z(64) | t1(64) | r(32) row-tiles x 64 kt
__device__ uint4 g_WheF[64 * 32 * 32 * 2];    // hh: 64 row-tiles x 32 kt (K=512)
// ---------------- fragment-layout state (B-frags) ----------------
__device__ uint4 g_hF[64 * 4 * 32];
__device__ uint4 g_h1F[64 * 4 * 32];
__device__ uint4 g_rwF[32 * 4 * 32];
// ---------------- logits GEMM fragments ----------------
// Wo B-frags: per k16n8 tile per lane uint4 {hi_b0,hi_b1,lo_b0,lo_b1}; idx (nt*64+kt)*32+lane
__device__ uint4 g_WoF[4000 * 64 * 32];
// hs A-frags: per m16k16 tile per lane 2x uint4 (hi,lo); idx ((mt*64+kt)*32+lane)*2
__device__ uint4 g_hsF[64 * 64 * 32 * 2];

__device__ __forceinline__ float sigf(float x) { return 1.f / (1.f + expf(-x)); }

__device__ __forceinline__ u64 fma2(u64 a, u64 b, u64 c) {
    u64 d;
    asm("fma.rn.f32x2 %0, %1, %2, %3;" : "=l"(d) : "l"(a), "l"(b), "l"(c));
    return d;
}

__device__ __forceinline__ uint32_t smem_u32(const void* p) {
    uint32_t a;
    asm("{ .reg .u64 t; cvta.to.shared.u64 t, %1; cvt.u32.u64 %0, t; }" : "=r"(a) : "l"(p));
    return a;
}

// ================= mma.sync helpers (base-target PTX, HMMA) =================
__device__ __forceinline__ void ldsm_x4(uint32_t& r0, uint32_t& r1, uint32_t& r2, uint32_t& r3,
                                        uint32_t addr) {
    asm volatile("ldmatrix.sync.aligned.m8n8.x4.shared.b16 {%0,%1,%2,%3}, [%4];"
        : "=r"(r0), "=r"(r1), "=r"(r2), "=r"(r3) : "r"(addr));
}
__device__ __forceinline__ void mma16816(float* c, const uint32_t* a, const uint32_t* b) {
    asm volatile("mma.sync.aligned.m16n8k16.row.col.f32.bf16.bf16.f32 "
        "{%0,%1,%2,%3}, {%4,%5,%6,%7}, {%8,%9}, {%0,%1,%2,%3};"
        : "+f"(c[0]), "+f"(c[1]), "+f"(c[2]), "+f"(c[3])
        : "r"(a[0]), "r"(a[1]), "r"(a[2]), "r"(a[3]), "r"(b[0]), "r"(b[1]));
}

__device__ __forceinline__ uint32_t pack_bf16(float a, float b) {
    uint32_t lo = __bfloat16_as_ushort(__float2bfloat16_rn(a));
    uint32_t hi = __bfloat16_as_ushort(__float2bfloat16_rn(b));
    return lo | (hi << 16);
}
__device__ __forceinline__ void cvt_split(float4 v, uint2& hh, uint2& ll) {
    float hx = __bfloat162float(__float2bfloat16_rn(v.x));
    float hy = __bfloat162float(__float2bfloat16_rn(v.y));
    float hz = __bfloat162float(__float2bfloat16_rn(v.z));
    float hw = __bfloat162float(__float2bfloat16_rn(v.w));
    hh = make_uint2(pack_bf16(v.x, v.y), pack_bf16(v.z, v.w));
    ll = make_uint2(pack_bf16(v.x - hx, v.y - hy), pack_bf16(v.z - hz, v.w - hw));
}
__device__ __forceinline__ void split2(float a, float b, uint32_t& h, uint32_t& l) {
    float ah = __bfloat162float(__float2bfloat16_rn(a));
    float bh = __bfloat162float(__float2bfloat16_rn(b));
    h = pack_bf16(a, b);
    l = pack_bf16(a - ah, b - bh);
}

// ======= smem-pipelined split-bf16 GEMM (used for gx only) =======
#define MAT_B   10240
#define BUF_B   (4 * MAT_B)
#define GM_SMEM (2 * BUF_B)

__global__ void __launch_bounds__(256) gemm_mma(
    const float* __restrict__ A, const float* __restrict__ B,
    const float* __restrict__ bias, float* __restrict__ C,
    int K, int N)
{
    extern __shared__ char smem[];
    const uint32_t sb = smem_u32(smem);
    const int tid = threadIdx.x;
    const int wid = tid >> 5, lane = tid & 31;
    const int wm = wid >> 1, wn = wid & 1;
    const int mBase = blockIdx.x * 128;
    const int nBase = blockIdx.y * 128;
    const int NC = K >> 5;

    float acc[2][8][4];
#pragma unroll
    for (int mt = 0; mt < 2; mt++)
#pragma unroll
        for (int nt = 0; nt < 8; nt++)
#pragma unroll
            for (int q = 0; q < 4; q++) acc[mt][nt][q] = 0.f;

    int lrow[4], lq[4];
#pragma unroll
    for (int i = 0; i < 4; i++) {
        int idx = tid * 4 + i;
        lrow[i] = idx >> 3;
        lq[i] = idx & 7;
    }

    float4 ra[4], rb[4];
#pragma unroll
    for (int i = 0; i < 4; i++) {
        ra[i] = *(const float4*)(A + (size_t)(mBase + lrow[i]) * K + lq[i] * 4);
        rb[i] = *(const float4*)(B + (size_t)(nBase + lrow[i]) * K + lq[i] * 4);
    }
#pragma unroll
    for (int i = 0; i < 4; i++) {
        uint2 hh, ll;
        uint32_t off = (uint32_t)(lrow[i] * 80 + lq[i] * 8);
        cvt_split(ra[i], hh, ll);
        *(uint2*)(smem + off) = hh;
        *(uint2*)(smem + MAT_B + off) = ll;
        cvt_split(rb[i], hh, ll);
        *(uint2*)(smem + 2 * MAT_B + off) = hh;
        *(uint2*)(smem + 3 * MAT_B + off) = ll;
    }
    __syncthreads();

    const uint32_t a_ls = (uint32_t)(wm * 32 + (lane & 15)) * 80 + (lane >> 4) * 16;
    const uint32_t b_ls = (uint32_t)(wn * 64 + (lane & 15)) * 80 + (lane >> 4) * 16;

    for (int c = 0; c < NC; c++) {
        const int p = c & 1;
        const uint32_t bufb = sb + p * BUF_B;

        if (c + 1 < NC) {
            const int kc = (c + 1) * 32;
#pragma unroll
            for (int i = 0; i < 4; i++) {
                ra[i] = *(const float4*)(A + (size_t)(mBase + lrow[i]) * K + kc + lq[i] * 4);
                rb[i] = *(const float4*)(B + (size_t)(nBase + lrow[i]) * K + kc + lq[i] * 4);
            }
        }

#pragma unroll
        for (int ks = 0; ks < 2; ks++) {
            uint32_t ahi[2][4], alo[2][4];
#pragma unroll
            for (int mt = 0; mt < 2; mt++) {
                uint32_t off = a_ls + mt * 16 * 80 + ks * 32;
                ldsm_x4(ahi[mt][0], ahi[mt][1], ahi[mt][2], ahi[mt][3], bufb + off);
                ldsm_x4(alo[mt][0], alo[mt][1], alo[mt][2], alo[mt][3], bufb + MAT_B + off);
            }
            uint32_t bhi[8][2], blo[8][2];
#pragma unroll
            for (int g = 0; g < 4; g++) {
                uint32_t off = b_ls + g * 16 * 80 + ks * 32;
                uint32_t r0, r1, r2, r3;
                ldsm_x4(r0, r1, r2, r3, bufb + 2 * MAT_B + off);
                bhi[2 * g][0] = r0; bhi[2 * g][1] = r2;
                bhi[2 * g + 1][0] = r1; bhi[2 * g + 1][1] = r3;
                ldsm_x4(r0, r1, r2, r3, bufb + 3 * MAT_B + off);
                blo[2 * g][0] = r0; blo[2 * g][1] = r2;
                blo[2 * g + 1][0] = r1; blo[2 * g + 1][1] = r3;
            }
#pragma unroll
            for (int mt = 0; mt < 2; mt++)
#pragma unroll
                for (int nt = 0; nt < 8; nt++) {
                    mma16816(acc[mt][nt], ahi[mt], bhi[nt]);
                    mma16816(acc[mt][nt], ahi[mt], blo[nt]);
                    mma16816(acc[mt][nt], alo[mt], bhi[nt]);
                }
        }

        if (c + 1 < NC) {
            char* dst = smem + (p ^ 1) * BUF_B;
#pragma unroll
            for (int i = 0; i < 4; i++) {
                uint2 hh, ll;
                uint32_t off = (uint32_t)(lrow[i] * 80 + lq[i] * 8);
                cvt_split(ra[i], hh, ll);
                *(uint2*)(dst + off) = hh;
                *(uint2*)(dst + MAT_B + off) = ll;
                cvt_split(rb[i], hh, ll);
                *(uint2*)(dst + 2 * MAT_B + off) = hh;
                *(uint2*)(dst + 3 * MAT_B + off) = ll;
            }
        }
        __syncthreads();
    }

#pragma unroll
    for (int mt = 0; mt < 2; mt++) {
        const int row0 = mBase + wm * 32 + mt * 16 + (lane >> 2);
#pragma unroll
        for (int nt = 0; nt < 8; nt++) {
            const int col = nBase + wn * 64 + nt * 8 + (lane & 3) * 2;
            float2 bv = *(const float2*)(bias + col);
            float2 o0 = make_float2(acc[mt][nt][0] + bv.x, acc[mt][nt][1] + bv.y);
            float2 o1 = make_float2(acc[mt][nt][2] + bv.x, acc[mt][nt][3] + bv.y);
            *(float2*)(C + (size_t)row0 * N + col) = o0;
            *(float2*)(C + (size_t)(row0 + 8) * N + col) = o1;
        }
    }
}

// ======= fragment-fed logits GEMM: C[1024,32000] = hsF @ WoF^T + bo =======
// grid(8, 250), 256 thr = 8 warps (4m x 2n); warp tile 32x64 (2mt x 8nt).
// Mainloop: pure LDG frags + MMA. No smem, no syncs.
__global__ void __launch_bounds__(256) gemm_logits(
    const float* __restrict__ bias, float* __restrict__ C)
{
    const int tid = threadIdx.x, lane = tid & 31, wid = tid >> 5;
    const int wm = wid >> 1, wn = wid & 1;
    const int mt0 = blockIdx.x * 8 + wm * 2;
    const int nt0 = blockIdx.y * 16 + wn * 8;

    float acc[2][8][4];
#pragma unroll
    for (int mtl = 0; mtl < 2; mtl++)
#pragma unroll
        for (int nt = 0; nt < 8; nt++)
#pragma unroll
            for (int q = 0; q < 4; q++) acc[mtl][nt][q] = 0.f;

#pragma unroll 2
    for (int kt = 0; kt < 64; kt++) {
        uint4 a[2][2];
#pragma unroll
        for (int mtl = 0; mtl < 2; mtl++) {
            const uint4* ap = g_hsF + ((size_t)((mt0 + mtl) * 64 + kt) * 32 + lane) * 2;
            a[mtl][0] = ap[0];
            a[mtl][1] = ap[1];
        }
#pragma unroll
        for (int nt = 0; nt < 8; nt++) {
            uint4 bv = g_WoF[((size_t)(nt0 + nt) * 64 + kt) * 32 + lane];
            uint32_t bh[2] = {bv.x, bv.y};
            uint32_t bl[2] = {bv.z, bv.w};
#pragma unroll
            for (int mtl = 0; mtl < 2; mtl++) {
                mma16816(acc[mtl][nt], (const uint32_t*)&a[mtl][0], bh);
                mma16816(acc[mtl][nt], (const uint32_t*)&a[mtl][0], bl);
                mma16816(acc[mtl][nt], (const uint32_t*)&a[mtl][1], bh);
            }
        }
    }

#pragma unroll
    for (int mtl = 0; mtl < 2; mtl++) {
        const int row0 = blockIdx.x * 128 + wm * 32 + mtl * 16 + (lane >> 2);
#pragma unroll
        for (int nt = 0; nt < 8; nt++) {
            const int col = blockIdx.y * 128 + wn * 64 + nt * 8 + (lane & 3) * 2;
            float2 bv = *(const float2*)(bias + col);
            float2 o0 = make_float2(acc[mtl][nt][0] + bv.x, acc[mtl][nt][1] + bv.y);
            float2 o1 = make_float2(acc[mtl][nt][2] + bv.x, acc[mtl][nt][3] + bv.y);
            *(float2*)(C + (size_t)row0 * 32000 + col) = o0;
            *(float2*)(C + (size_t)(row0 + 8) * 32000 + col) = o1;
        }
    }
}

// ---------------- Wo -> B-fragment conversion (runs once) ----------------
__global__ void __launch_bounds__(256) k_convWo(const float* __restrict__ Wo)
{
    int g = blockIdx.x * 256 + threadIdx.x;
    if (g >= 4000 * 64 * 32) return;
    int lane = g & 31;
    int kt = (g >> 5) & 63;
    int nt = g >> 11;
    int n = nt * 8 + (lane >> 2);
    int k0 = kt * 16 + (lane & 3) * 2;
    const float* p = Wo + (size_t)n * 1024 + k0;
    uint32_t h0, l0, h1, l1;
    split2(p[0], p[1], h0, l0);
    split2(p[8], p[9], h1, l1);
    g_WoF[g] = make_uint4(h0, h1, l0, l1);
}

// ---------------- recurrence weight fragment conversion (runs once) ----------------
__global__ void __launch_bounds__(256) k_convW(
    const float* __restrict__ Whh, const float* __restrict__ Wz,
    const float* __restrict__ Wh, const float* __restrict__ Wr)
{
    int g = blockIdx.x * 256 + threadIdx.x;
    if (g >= 28672 * 32) return;
    const int tile = g >> 5, lane = g & 31;
    const int rl = lane >> 2;
    const int kq = (lane & 3) * 2;
    const float *r0p, *r8p;
    uint4* dst;
    if (tile < 16384) {
        int rt = tile >> 6, kt = tile & 63;
        int j0 = (rt >> 1) * 8;
        int gate_lo = (rt & 1) * 2;
        int k0 = kt * 16 + kq;
        r0p = Whh + (size_t)(gate_lo * 1024 + j0 + rl) * 1024 + k0;
        r8p = Whh + (size_t)((gate_lo + 1) * 1024 + j0 + rl) * 1024 + k0;
        dst = g_WhhF + ((size_t)tile * 32 + lane) * 2;
    } else if (tile < 26624) {
        int t2 = tile - 16384;
        int rt = t2 >> 6, kt = t2 & 63;
        int k0 = kt * 16 + kq;
        const float* base;
        int row;
        if (rt < 64)      { base = Wz; row = rt * 16; }
        else if (rt < 128){ base = Wh; row = (rt - 64) * 16; }
        else              { base = Wr; row = (rt - 128) * 16; }
        r0p = base + (size_t)(row + rl) * 1536 + 512 + k0;
        r8p = base + (size_t)(row + rl + 8) * 1536 + 512 + k0;
        dst = g_WzrF + ((size_t)t2 * 32 + lane) * 2;
    } else {
        int t3 = tile - 26624;
        int rt = t3 >> 5, kt = t3 & 31;
        int k0 = kt * 16 + kq;
        r0p = Wh + (size_t)(rt * 16 + rl) * 1536 + k0;
        r8p = Wh + (size_t)(rt * 16 + rl + 8) * 1536 + k0;
        dst = g_WheF + ((size_t)t3 * 32 + lane) * 2;
    }
    uint4 hi, lo;
    split2(r0p[0], r0p[1], hi.x, lo.x);
    split2(r8p[0], r8p[1], hi.y, lo.y);
    split2(r0p[8], r0p[9], hi.z, lo.z);
    split2(r8p[8], r8p[9], hi.w, lo.w);
    dst[0] = hi;
    dst[1] = lo;
}

// ---------------- shared step-MMA slice (no smem operands) ----------------
__device__ __forceinline__ void step_mma_slice(
    const uint4* __restrict__ Af, const uint4* __restrict__ Bf,
    int rt, int ktTot, int kt0, int ktN, int lane, float acc[4][4])
{
#pragma unroll 2
    for (int kt = kt0; kt < kt0 + ktN; kt++) {
        const uint4* ap = Af + (((size_t)rt * ktTot + kt) * 32 + lane) * 2;
        uint4 ahi = ap[0];
        uint4 alo = ap[1];
        const uint4* bp = Bf + (size_t)(kt * 4) * 32 + lane;
        uint4 bv0 = bp[0], bv1 = bp[32], bv2 = bp[64], bv3 = bp[96];
        uint4 bvs[4] = {bv0, bv1, bv2, bv3};
#pragma unroll
        for (int nt = 0; nt < 4; nt++) {
            uint32_t bh2[2] = {bvs[nt].x, bvs[nt].y};
            uint32_t bl2[2] = {bvs[nt].z, bvs[nt].w};
            mma16816(acc[nt], (const uint32_t*)&ahi, bh2);
            mma16816(acc[nt], (const uint32_t*)&ahi, bl2);
            mma16816(acc[nt], (const uint32_t*)&alo, bh2);
        }
    }
}

__device__ __forceinline__ void store_cfrag(float S[8][16][33], int wid, int lane,
                                            float acc[4][4])
{
    int r = lane >> 2, c0 = (lane & 3) * 2;
#pragma unroll
    for (int nt = 0; nt < 4; nt++) {
        S[wid][r][nt * 8 + c0]     = acc[nt][0];
        S[wid][r][nt * 8 + c0 + 1] = acc[nt][1];
        S[wid][r + 8][nt * 8 + c0]     = acc[nt][2];
        S[wid][r + 8][nt * 8 + c0 + 1] = acc[nt][3];
    }
}

// ---------------- step 1: gates MMA + LSTM pointwise ----------------
__global__ void __launch_bounds__(256) gates_mma(int t)
{
    __shared__ float S[8][16][33];
    const int tid = threadIdx.x, lane = tid & 31, wid = tid >> 5;
    const int bid = blockIdx.x;
    const int mt = wid & 1, ks = wid >> 1;
    float acc[4][4] = {};
    step_mma_slice(g_WhhF, g_hF, bid * 2 + mt, 64, ks * 16, 16, lane, acc);
    store_cfrag(S, wid, lane, acc);
    __syncthreads();

    const int jl = tid >> 5, b = tid & 31;
    const int j = bid * 8 + jl;
    float gi = 0, gf = 0, gg = 0, go = 0;
#pragma unroll
    for (int k = 0; k < 4; k++) {
        gi += S[k * 2][jl][b];     gf += S[k * 2][jl + 8][b];
        gg += S[k * 2 + 1][jl][b]; go += S[k * 2 + 1][jl + 8][b];
    }
    const float* gx = g_gx + (size_t)(t * 32 + b) * 4096 + j;
    gi += gx[0]; gf += gx[1024]; gg += gx[2048]; go += gx[3072];
    float c = g_cT[j * 32 + b];
    float cn = sigf(gf) * c + sigf(gi) * tanhf(gg);
    g_cT[j * 32 + b] = cn;
    float h1 = sigf(go) * tanhf(cn);
    g_h1T[j * 32 + b] = h1;
    __syncthreads();
    S[0][jl][b] = h1;
    __syncthreads();
    if (tid < 128) {
        int nt = tid >> 5, l = tid & 31;
        int k0l = (l & 3) * 2, n = nt * 8 + (l >> 2);
        uint32_t hh_, ll_;
        split2(S[0][k0l][n], S[0][k0l + 1][n], hh_, ll_);
        int kt = bid >> 1, half = bid & 1;
        uint32_t* d = (uint32_t*)&g_h1F[(kt * 4 + nt) * 32 + l];
        d[half] = hh_;
        d[2 + half] = ll_;
    }
}

// ---------------- step 2: z / t1 / r*we MMA ----------------
__global__ void __launch_bounds__(256) zrt_mma()
{
    __shared__ float S[8][16][33];
    const int tid = threadIdx.x, lane = tid & 31, wid = tid >> 5;
    const int bid = blockIdx.x;
    const int mt = wid & 1, ks = wid >> 1;
    float acc[4][4] = {};
    step_mma_slice(g_WzrF, g_h1F, bid * 2 + mt, 64, ks * 16, 16, lane, acc);
    store_cfrag(S, wid, lane, acc);
    __syncthreads();

    const int m = tid >> 3, nq = (tid & 7) * 4;
    float v[4];
#pragma unroll
    for (int q = 0; q < 4; q++) {
        float s = 0;
#pragma unroll
        for (int k = 0; k < 4; k++) s += S[(k << 1) | (m >> 4)][m & 15][nq + q];
        v[q] = s;
    }
    if (bid < 32) {
        int j = bid * 32 + m;
#pragma unroll
        for (int q = 0; q < 4; q++)
            g_zT[j * 32 + nq + q] = sigf(g_zcT[j * 32 + nq + q] + v[q]);
    } else if (bid < 64) {
        int j = (bid - 32) * 32 + m;
#pragma unroll
        for (int q = 0; q < 4; q++) g_t1T[j * 32 + nq + q] = v[q];
    } else {
        int e = (bid - 64) * 32 + m;
        float rw[4];
#pragma unroll
        for (int q = 0; q < 4; q++)
            rw[q] = sigf(g_rcT[e * 32 + nq + q] + v[q]) * g_weT[e * 32 + nq + q];
        __syncthreads();
        float (*S2)[33] = (float(*)[33])S;
#pragma unroll
        for (int q = 0; q < 4; q++) S2[m][nq + q] = rw[q];
        __syncthreads();
        int ktl = tid >> 7, nt = (tid >> 5) & 3, l = tid & 31;
        int k0l = ktl * 16 + (l & 3) * 2, n = nt * 8 + (l >> 2);
        uint32_t h0, l0, h1, l1;
        split2(S2[k0l][n],     S2[k0l + 1][n], h0, l0);
        split2(S2[k0l + 8][n], S2[k0l + 9][n], h1, l1);
        int kt = (bid - 64) * 2 + ktl;
        g_rwF[(kt * 4 + nt) * 32 + l] = make_uint4(h0, h1, l0, l1);
    }
}

// ---------------- step 3: hh MMA + h update + hF/hsF frag writes ----------------
__global__ void __launch_bounds__(256) hh_mma(const float* __restrict__ bh, int t)
{
    __shared__ float S[8][16][33];
    const int tid = threadIdx.x, lane = tid & 31, wid = tid >> 5;
    const int bid = blockIdx.x;
    const int mt = wid & 1, ks = wid >> 1;
    float acc[4][4] = {};
    step_mma_slice(g_WheF, g_rwF, bid * 2 + mt, 32, ks * 8, 8, lane, acc);
    store_cfrag(S, wid, lane, acc);
    __syncthreads();

    const int m = tid >> 3, nq = (tid & 7) * 4;
    float v[4];
#pragma unroll
    for (int q = 0; q < 4; q++) {
        float s = 0;
#pragma unroll
        for (int k = 0; k < 4; k++) s += S[(k << 1) | (m >> 4)][m & 15][nq + q];
        v[q] = s;
    }
    const int j = bid * 32 + m;
    const float bhv = bh[j];
    float hn[4];
#pragma unroll
    for (int q = 0; q < 4; q++) {
        int b = nq + q;
        float hh = tanhf(g_t1T[j * 32 + b] + v[q] + bhv);
        float z = g_zT[j * 32 + b];
        float h1 = g_h1T[j * 32 + b];
        hn[q] = (1.f - z) * h1 + z * hh;
        g_hT[j * 32 + b] = hn[q];
    }
    __syncthreads();
    float (*S2)[33] = (float(*)[33])S;    // S2[j_local][b]
#pragma unroll
    for (int q = 0; q < 4; q++) S2[m][nq + q] = hn[q];
    __syncthreads();
    {   // B-frag write for next-step h (g_hF)
        int ktl = tid >> 7, nt = (tid >> 5) & 3, l = tid & 31;
        int k0l = ktl * 16 + (l & 3) * 2, n = nt * 8 + (l >> 2);
        uint32_t h0, l0, h1, l1;
        split2(S2[k0l][n],     S2[k0l + 1][n], h0, l0);
        split2(S2[k0l + 8][n], S2[k0l + 9][n], h1, l1);
        int kt = bid * 2 + ktl;
        g_hF[(kt * 4 + nt) * 32 + l] = make_uint4(h0, h1, l0, l1);
    }
    if (tid < 128) {   // A-frag write for logits GEMM (g_hsF): rows t*32+b, cols j
        int sub = tid >> 5, l = tid & 31;
        int mtl = sub & 1, ktl = sub >> 1;
        int r = l >> 2, kq = (l & 3) * 2;
        int k0 = ktl * 16 + kq, br = mtl * 16 + r;
        uint4 hi, lo;
        split2(S2[k0][br],      S2[k0 + 1][br],      hi.x, lo.x);
        split2(S2[k0][br + 8],  S2[k0 + 1][br + 8],  hi.y, lo.y);
        split2(S2[k0 + 8][br],  S2[k0 + 9][br],      hi.z, lo.z);
        split2(S2[k0 + 8][br + 8], S2[k0 + 9][br + 8], hi.w, lo.w);
        int mtg = 2 * t + mtl, ktg = bid * 2 + ktl;
        uint4* d = g_hsF + ((size_t)(mtg * 64 + ktg) * 32 + l) * 2;
        d[0] = hi;
        d[1] = lo;
    }
}

// ---------------- gather: we (transposed), se, bias sum ----------------
__global__ void k_gather(const int* __restrict__ word, const int* __restrict__ seq,
                         const float* __restrict__ emb,
                         const float* __restrict__ bih, const float* __restrict__ bhh)
{
    int idx = blockIdx.x * blockDim.x + threadIdx.x;
    if (idx < 1024 * 512) {
        int m = idx >> 9, e = idx & 511;
        g_se[idx] = emb[(size_t)seq[m] * 512 + e];
    }
    if (idx < 512 * 32) {
        int e = idx >> 5, b = idx & 31;
        g_weT[idx] = emb[(size_t)word[b] * 512 + e];
    }
    if (idx < 4096) g_bsum[idx] = bih[idx] + bhh[idx];
}

// ================= fp32 micro-GEMM core (prep only) =================
template<int T>
__device__ __forceinline__ void gemm_core(
    float (*As)[16][64], float (*Bs)[16][32], float (*Red)[32][32],
    const float* arow, const float* brow, int kg, int s)
{
    const int r = s >> 1, kofs = (s & 1) * 8;
    const int bk = s >> 2, bofs = (s & 3) * 8;
    const int mthr = s >> 3, nthr = s & 7;
    const int m0 = mthr * 4, n0 = nthr * 4;

    u64 acc[4][2];
#pragma unroll
    for (int i = 0; i < 4; i++) { acc[i][0] = 0ull; acc[i][1] = 0ull; }

    const float* aP = arow + kofs;
    const float* bP = brow + bk * 32 + bofs;

    float4 a0 = *(const float4*)aP;
    float4 a1 = *(const float4*)(aP + 4);
    float4 b0 = *(const float4*)bP;
    float4 b1 = *(const float4*)(bP + 4);

#pragma unroll 1
    for (int t = 0; t < T; t++) {
        {
            float va[8] = {a0.x, a0.y, a0.z, a0.w, a1.x, a1.y, a1.z, a1.w};
#pragma unroll
            for (int i = 0; i < 8; i++) {
                float2 d = make_float2(va[i], va[i]);
                *(float2*)&As[kg][kofs + i][2 * r] = d;
            }
            *(float4*)&Bs[kg][bk][bofs]     = b0;
            *(float4*)&Bs[kg][bk][bofs + 4] = b1;
        }
        __syncthreads();
        if (t + 1 < T) {
            aP += 16; bP += 512;
            a0 = *(const float4*)aP;
            a1 = *(const float4*)(aP + 4);
            b0 = *(const float4*)bP;
            b1 = *(const float4*)(bP + 4);
        }
#pragma unroll
        for (int k = 0; k < 16; k++) {
            float4 av0 = *(const float4*)&As[kg][k][2 * m0];
            float4 av1 = *(const float4*)&As[kg][k][2 * m0 + 4];
            float4 bv  = *(const float4*)&Bs[kg][k][n0];
            const u64* ap0 = (const u64*)&av0;
            const u64* ap1 = (const u64*)&av1;
            const u64* bp  = (const u64*)&bv;
            acc[0][0] = fma2(ap0[0], bp[0], acc[0][0]);
            acc[0][1] = fma2(ap0[0], bp[1], acc[0][1]);
            acc[1][0] = fma2(ap0[1], bp[0], acc[1][0]);
            acc[1][1] = fma2(ap0[1], bp[1], acc[1][1]);
            acc[2][0] = fma2(ap1[0], bp[0], acc[2][0]);
            acc[2][1] = fma2(ap1[0], bp[1], acc[2][1]);
            acc[3][0] = fma2(ap1[1], bp[0], acc[3][0]);
            acc[3][1] = fma2(ap1[1], bp[1], acc[3][1]);
        }
        __syncthreads();
    }
#pragma unroll
    for (int i = 0; i < 4; i++) {
        *(float2*)&Red[kg][m0 + i][n0]     = *(float2*)&acc[i][0];
        *(float2*)&Red[kg][m0 + i][n0 + 2] = *(float2*)&acc[i][1];
    }
    __syncthreads();
}

// ---------------- prep: h0 (-> h,c,hF), zc, rc ----------------
__global__ void __launch_bounds__(256) k_prep2(
    const float* __restrict__ Wl, const float* __restrict__ bl,
    const float* __restrict__ Wz, const float* __restrict__ bz,
    const float* __restrict__ Wr, const float* __restrict__ br)
{
    __shared__ __align__(16) float As[4][16][64];
    __shared__ __align__(16) float Bs[4][16][32];
    __shared__ float Red[4][32][32];
    const int tid = threadIdx.x;
    const int kg = tid >> 6, s = tid & 63;
    const int mbase = blockIdx.x * 32;
    const int w = mbase + (s >> 1);
    const float* arow;
    if (w < 1024)      arow = Wl + (size_t)w * 512;
    else if (w < 2048) arow = Wz + (size_t)(w - 1024) * 1536;
    else               arow = Wr + (size_t)(w - 2048) * 1536;
    arow += kg * 128;
    const float* brow = g_weT + kg * 128 * 32;
    gemm_core<8>(As, Bs, Red, arow, brow, kg, s);

    const int m = tid >> 3, nq = (tid & 7) * 4;
    const int wo = mbase + m;
    float4 v0 = *(float4*)&Red[0][m][nq];
    float4 v1 = *(float4*)&Red[1][m][nq];
    float4 v2 = *(float4*)&Red[2][m][nq];
    float4 v3 = *(float4*)&Red[3][m][nq];
    float v[4] = { v0.x + v1.x + v2.x + v3.x, v0.y + v1.y + v2.y + v3.y,
                   v0.z + v1.z + v2.z + v3.z, v0.w + v1.w + v2.w + v3.w };
    if (wo < 1024) {
        float bb = bl[wo];
        float h0v[4];
#pragma unroll
        for (int q = 0; q < 4; q++) {
            h0v[q] = v[q] + bb;
            g_hT[wo * 32 + nq + q] = h0v[q];
            g_cT[wo * 32 + nq + q] = h0v[q];
        }
        __syncthreads();
        float (*S2)[33] = (float(*)[33])&As[0][0][0];
#pragma unroll
        for (int q = 0; q < 4; q++) S2[m][nq + q] = h0v[q];
        __syncthreads();
        int ktl = tid >> 7, nt = (tid >> 5) & 3, l = tid & 31;
        int k0l = ktl * 16 + (l & 3) * 2, n = nt * 8 + (l >> 2);
        uint32_t h0, l0, h1, l1;
        split2(S2[k0l][n],     S2[k0l + 1][n], h0, l0);
        split2(S2[k0l + 8][n], S2[k0l + 9][n], h1, l1);
        int kt = blockIdx.x * 2 + ktl;
        g_hF[(kt * 4 + nt) * 32 + l] = make_uint4(h0, h1, l0, l1);
    } else if (wo < 2048) {
        int i = wo - 1024; float bb = bz[i];
#pragma unroll
        for (int q = 0; q < 4; q++) g_zcT[i * 32 + nq + q] = v[q] + bb;
    } else {
        int e = wo - 2048; float bb = br[e];
#pragma unroll
        for (int q = 0; q < 4; q++) g_rcT[e * 32 + nq + q] = v[q] + bb;
    }
}

// ---------------- tail: hf, cf into output ----------------
__global__ void k_tail(float* __restrict__ out)
{
    int idx = blockIdx.x * blockDim.x + threadIdx.x;   // < 32768
    int b = idx >> 10, j = idx & 1023;
    out[32768000 + idx]         = g_hT[j * 32 + b];
    out[32768000 + 32768 + idx] = g_cT[j * 32 + b];
}

// ---------------- launch ----------------
extern "C" void kernel_launch(void* const* d_in, const int* in_sizes, int n_in,
                              void* d_out, int out_size)
{
    const int*   word = (const int*)d_in[0];
    const int*   seq  = (const int*)d_in[1];
    const float* emb  = (const float*)d_in[2];
    const float* Wl   = (const float*)d_in[3];
    const float* bl   = (const float*)d_in[4];
    const float* Wih  = (const float*)d_in[5];
    const float* Whh  = (const float*)d_in[6];
    const float* bih  = (const float*)d_in[7];
    const float* bhh  = (const float*)d_in[8];
    const float* Wz   = (const float*)d_in[9];
    const float* bz   = (const float*)d_in[10];
    const float* Wr   = (const float*)d_in[11];
    const float* br   = (const float*)d_in[12];
    const float* Wh   = (const float*)d_in[13];
    const float* bh   = (const float*)d_in[14];
    const float* Wo   = (const float*)d_in[15];
    const float* bo   = (const float*)d_in[16];
    float* out = (float*)d_out;

    void *p_se, *p_gx, *p_bsum;
    cudaGetSymbolAddress(&p_se, g_se);
    cudaGetSymbolAddress(&p_gx, g_gx);
    cudaGetSymbolAddress(&p_bsum, g_bsum);

    cudaFuncSetAttribute(gemm_mma, cudaFuncAttributeMaxDynamicSharedMemorySize, GM_SMEM);

    k_convW<<<3584, 256>>>(Whh, Wz, Wh, Wr);
    k_convWo<<<32000, 256>>>(Wo);
    k_gather<<<2048, 256>>>(word, seq, emb, bih, bhh);
    k_prep2<<<80, 256>>>(Wl, bl, Wz, bz, Wr, br);

    // gx = se @ Wih.T + (bih+bhh):  M=1024, N=4096, K=512  (HMMA split-bf16)
    gemm_mma<<<dim3(8, 32), 256, GM_SMEM>>>((const float*)p_se, Wih,
                                            (const float*)p_bsum, (float*)p_gx,
                                            512, 4096);

    for (int t = 0; t < 32; t++) {
        gates_mma<<<128, 256>>>(t);
        zrt_mma<<<80, 256>>>();
        hh_mma<<<32, 256>>>(bh, t);
    }

    // logits = hsF @ WoF^T + bo  (fragment-fed HMMA, no smem)
    gemm_logits<<<dim3(8, 250), 256>>>(bo, out);

    k_tail<<<128, 256>>>(out);
}

// round 17
// speedup vs baseline: 5.5064x; 1.1809x over previous
#include <cuda_runtime.h>
#include <cuda_bf16.h>
#include <math.h>
#include <stdint.h>

typedef unsigned long long u64;

// ---------------- scratch (device globals; no allocs allowed) ----------------
__device__ float g_weT[512 * 32];        // we transposed [e][b]
__device__ float g_se[1024 * 512];       // se [(t*32+b)][e]
__device__ float g_bsum[4096];           // bih + bhh
__device__ float g_gx[1024 * 4096];      // se @ Wih.T + bsum   [(t*32+b)][4H]
__device__ float g_hT[1024 * 32];        // h  [j][b]
__device__ float g_cT[1024 * 32];        // c  [j][b]
__device__ float g_h1T[1024 * 32];       // post-LSTM h [j][b]
__device__ float g_zcT[1024 * 32];       // we-part of z preact [j][b]
__device__ float g_rcT[512 * 32];        // we-part of r preact [e][b]
__device__ float g_zT[1024 * 32];        // z [j][b]
__device__ float g_t1T[1024 * 32];       // h1 @ Wh_h.T [j][b]

// ---------------- fragment-layout weights (hi/lo split bf16) ----------------
__device__ uint4 g_WhhF[256 * 64 * 32 * 2];   // gates: 256 row-tiles (gate-paired) x 64 kt
__device__ uint4 g_WzrF[160 * 64 * 32 * 2];   // z(64) | t1(64) | r(32) row-tiles x 64 kt
__device__ uint4 g_WheF[64 * 32 * 32 * 2];    // hh: 64 row-tiles x 32 kt (K=512)
// ---------------- fragment-layout state (B-frags) ----------------
__device__ uint4 g_hF[64 * 4 * 32];
__device__ uint4 g_h1F[64 * 4 * 32];
__device__ uint4 g_rwF[32 * 4 * 32];
// ---------------- logits GEMM fragments ----------------
__device__ uint4 g_WoF[4000 * 64 * 32];       // B-frags {hi_b0,hi_b1,lo_b0,lo_b1}
__device__ uint4 g_hsF[64 * 64 * 32 * 2];     // A-frags (hi,lo) pairs

__device__ __forceinline__ float sigf(float x) { return 1.f / (1.f + expf(-x)); }

__device__ __forceinline__ u64 fma2(u64 a, u64 b, u64 c) {
    u64 d;
    asm("fma.rn.f32x2 %0, %1, %2, %3;" : "=l"(d) : "l"(a), "l"(b), "l"(c));
    return d;
}

__device__ __forceinline__ uint32_t smem_u32(const void* p) {
    uint32_t a;
    asm("{ .reg .u64 t; cvta.to.shared.u64 t, %1; cvt.u32.u64 %0, t; }" : "=r"(a) : "l"(p));
    return a;
}

// ================= mma.sync helpers (base-target PTX, HMMA) =================
__device__ __forceinline__ void ldsm_x4(uint32_t& r0, uint32_t& r1, uint32_t& r2, uint32_t& r3,
                                        uint32_t addr) {
    asm volatile("ldmatrix.sync.aligned.m8n8.x4.shared.b16 {%0,%1,%2,%3}, [%4];"
        : "=r"(r0), "=r"(r1), "=r"(r2), "=r"(r3) : "r"(addr));
}
__device__ __forceinline__ void mma16816(float* c, const uint32_t* a, const uint32_t* b) {
    asm volatile("mma.sync.aligned.m16n8k16.row.col.f32.bf16.bf16.f32 "
        "{%0,%1,%2,%3}, {%4,%5,%6,%7}, {%8,%9}, {%0,%1,%2,%3};"
        : "+f"(c[0]), "+f"(c[1]), "+f"(c[2]), "+f"(c[3])
        : "r"(a[0]), "r"(a[1]), "r"(a[2]), "r"(a[3]), "r"(b[0]), "r"(b[1]));
}

__device__ __forceinline__ uint32_t pack_bf16(float a, float b) {
    uint32_t lo = __bfloat16_as_ushort(__float2bfloat16_rn(a));
    uint32_t hi = __bfloat16_as_ushort(__float2bfloat16_rn(b));
    return lo | (hi << 16);
}
__device__ __forceinline__ void cvt_split(float4 v, uint2& hh, uint2& ll) {
    float hx = __bfloat162float(__float2bfloat16_rn(v.x));
    float hy = __bfloat162float(__float2bfloat16_rn(v.y));
    float hz = __bfloat162float(__float2bfloat16_rn(v.z));
    float hw = __bfloat162float(__float2bfloat16_rn(v.w));
    hh = make_uint2(pack_bf16(v.x, v.y), pack_bf16(v.z, v.w));
    ll = make_uint2(pack_bf16(v.x - hx, v.y - hy), pack_bf16(v.z - hz, v.w - hw));
}
__device__ __forceinline__ void split2(float a, float b, uint32_t& h, uint32_t& l) {
    float ah = __bfloat162float(__float2bfloat16_rn(a));
    float bh = __bfloat162float(__float2bfloat16_rn(b));
    h = pack_bf16(a, b);
    l = pack_bf16(a - ah, b - bh);
}

// ======= smem-pipelined split-bf16 GEMM (used for gx only) =======
#define MAT_B   10240
#define BUF_B   (4 * MAT_B)
#define GM_SMEM (2 * BUF_B)

__global__ void __launch_bounds__(256) gemm_mma(
    const float* __restrict__ A, const float* __restrict__ B,
    const float* __restrict__ bias, float* __restrict__ C,
    int K, int N)
{
    extern __shared__ char smem[];
    const uint32_t sb = smem_u32(smem);
    const int tid = threadIdx.x;
    const int wid = tid >> 5, lane = tid & 31;
    const int wm = wid >> 1, wn = wid & 1;
    const int mBase = blockIdx.x * 128;
    const int nBase = blockIdx.y * 128;
    const int NC = K >> 5;

    float acc[2][8][4];
#pragma unroll
    for (int mt = 0; mt < 2; mt++)
#pragma unroll
        for (int nt = 0; nt < 8; nt++)
#pragma unroll
            for (int q = 0; q < 4; q++) acc[mt][nt][q] = 0.f;

    int lrow[4], lq[4];
#pragma unroll
    for (int i = 0; i < 4; i++) {
        int idx = tid * 4 + i;
        lrow[i] = idx >> 3;
        lq[i] = idx & 7;
    }

    float4 ra[4], rb[4];
#pragma unroll
    for (int i = 0; i < 4; i++) {
        ra[i] = *(const float4*)(A + (size_t)(mBase + lrow[i]) * K + lq[i] * 4);
        rb[i] = *(const float4*)(B + (size_t)(nBase + lrow[i]) * K + lq[i] * 4);
    }
#pragma unroll
    for (int i = 0; i < 4; i++) {
        uint2 hh, ll;
        uint32_t off = (uint32_t)(lrow[i] * 80 + lq[i] * 8);
        cvt_split(ra[i], hh, ll);
        *(uint2*)(smem + off) = hh;
        *(uint2*)(smem + MAT_B + off) = ll;
        cvt_split(rb[i], hh, ll);
        *(uint2*)(smem + 2 * MAT_B + off) = hh;
        *(uint2*)(smem + 3 * MAT_B + off) = ll;
    }
    __syncthreads();

    const uint32_t a_ls = (uint32_t)(wm * 32 + (lane & 15)) * 80 + (lane >> 4) * 16;
    const uint32_t b_ls = (uint32_t)(wn * 64 + (lane & 15)) * 80 + (lane >> 4) * 16;

    for (int c = 0; c < NC; c++) {
        const int p = c & 1;
        const uint32_t bufb = sb + p * BUF_B;

        if (c + 1 < NC) {
            const int kc = (c + 1) * 32;
#pragma unroll
            for (int i = 0; i < 4; i++) {
                ra[i] = *(const float4*)(A + (size_t)(mBase + lrow[i]) * K + kc + lq[i] * 4);
                rb[i] = *(const float4*)(B + (size_t)(nBase + lrow[i]) * K + kc + lq[i] * 4);
            }
        }

#pragma unroll
        for (int ks = 0; ks < 2; ks++) {
            uint32_t ahi[2][4], alo[2][4];
#pragma unroll
            for (int mt = 0; mt < 2; mt++) {
                uint32_t off = a_ls + mt * 16 * 80 + ks * 32;
                ldsm_x4(ahi[mt][0], ahi[mt][1], ahi[mt][2], ahi[mt][3], bufb + off);
                ldsm_x4(alo[mt][0], alo[mt][1], alo[mt][2], alo[mt][3], bufb + MAT_B + off);
            }
            uint32_t bhi[8][2], blo[8][2];
#pragma unroll
            for (int g = 0; g < 4; g++) {
                uint32_t off = b_ls + g * 16 * 80 + ks * 32;
                uint32_t r0, r1, r2, r3;
                ldsm_x4(r0, r1, r2, r3, bufb + 2 * MAT_B + off);
                bhi[2 * g][0] = r0; bhi[2 * g][1] = r2;
                bhi[2 * g + 1][0] = r1; bhi[2 * g + 1][1] = r3;
                ldsm_x4(r0, r1, r2, r3, bufb + 3 * MAT_B + off);
                blo[2 * g][0] = r0; blo[2 * g][1] = r2;
                blo[2 * g + 1][0] = r1; blo[2 * g + 1][1] = r3;
            }
#pragma unroll
            for (int mt = 0; mt < 2; mt++)
#pragma unroll
                for (int nt = 0; nt < 8; nt++) {
                    mma16816(acc[mt][nt], ahi[mt], bhi[nt]);
                    mma16816(acc[mt][nt], ahi[mt], blo[nt]);
                    mma16816(acc[mt][nt], alo[mt], bhi[nt]);
                }
        }

        if (c + 1 < NC) {
            char* dst = smem + (p ^ 1) * BUF_B;
#pragma unroll
            for (int i = 0; i < 4; i++) {
                uint2 hh, ll;
                uint32_t off = (uint32_t)(lrow[i] * 80 + lq[i] * 8);
                cvt_split(ra[i], hh, ll);
                *(uint2*)(dst + off) = hh;
                *(uint2*)(dst + MAT_B + off) = ll;
                cvt_split(rb[i], hh, ll);
                *(uint2*)(dst + 2 * MAT_B + off) = hh;
                *(uint2*)(dst + 3 * MAT_B + off) = ll;
            }
        }
        __syncthreads();
    }

#pragma unroll
    for (int mt = 0; mt < 2; mt++) {
        const int row0 = mBase + wm * 32 + mt * 16 + (lane >> 2);
#pragma unroll
        for (int nt = 0; nt < 8; nt++) {
            const int col = nBase + wn * 64 + nt * 8 + (lane & 3) * 2;
            float2 bv = *(const float2*)(bias + col);
            float2 o0 = make_float2(acc[mt][nt][0] + bv.x, acc[mt][nt][1] + bv.y);
            float2 o1 = make_float2(acc[mt][nt][2] + bv.x, acc[mt][nt][3] + bv.y);
            *(float2*)(C + (size_t)row0 * N + col) = o0;
            *(float2*)(C + (size_t)(row0 + 8) * N + col) = o1;
        }
    }
}

// ======= fragment-fed logits GEMM with smem dedup staging =======
// grid(8, 250), 256 thr = 8 warps (4m x 2n); CTA tile 128x128.
// Per kt: stage A frags (8 KB) + B frags (8 KB) ONCE via coalesced LDG->STS,
// double buffered; warps read via LDS.128. Kills the 4x/2x intra-CTA LDG
// redundancy (6 GB -> 2 GB L2 traffic).
__global__ void __launch_bounds__(256) gemm_logits(
    const float* __restrict__ bias, float* __restrict__ C)
{
    __shared__ __align__(16) uint4 As[2][8][64];   // [buf][mtL][lane*2+h]
    __shared__ __align__(16) uint4 Bs[2][16][32];  // [buf][ntL][lane]
    const int tid = threadIdx.x, lane = tid & 31, wid = tid >> 5;
    const int wm = wid >> 1, wn = wid & 1;
    const int mtBase = blockIdx.x * 8;
    const int ntBase = blockIdx.y * 16;

    float acc[2][8][4];
#pragma unroll
    for (int mtl = 0; mtl < 2; mtl++)
#pragma unroll
        for (int nt = 0; nt < 8; nt++)
#pragma unroll
            for (int q = 0; q < 4; q++) acc[mtl][nt][q] = 0.f;

    // loader indices (per thread, fixed): A covers 512 uint4, B covers 512 uint4
    const int aMt0 = tid >> 6, aLi0 = tid & 63;
    const int bNt0 = tid >> 5, bLi0 = tid & 31;

#define STAGE(kt, buf)                                                          \
    {                                                                           \
        As[buf][aMt0][aLi0] =                                                   \
            g_hsF[((size_t)((mtBase + aMt0) * 64 + (kt)) * 32) * 2 + aLi0];     \
        As[buf][aMt0 + 4][aLi0] =                                               \
            g_hsF[((size_t)((mtBase + aMt0 + 4) * 64 + (kt)) * 32) * 2 + aLi0]; \
        Bs[buf][bNt0][bLi0] =                                                   \
            g_WoF[((size_t)(ntBase + bNt0) * 64 + (kt)) * 32 + bLi0];           \
        Bs[buf][bNt0 + 8][bLi0] =                                               \
            g_WoF[((size_t)(ntBase + bNt0 + 8) * 64 + (kt)) * 32 + bLi0];       \
    }

    STAGE(0, 0);
    __syncthreads();

#pragma unroll 1
    for (int kt = 0; kt < 64; kt++) {
        const int p = kt & 1;
        uint4 na0, na1, nb0, nb1;
        if (kt + 1 < 64) {   // prefetch next tile into regs (overlaps MMAs)
            na0 = g_hsF[((size_t)((mtBase + aMt0) * 64 + kt + 1) * 32) * 2 + aLi0];
            na1 = g_hsF[((size_t)((mtBase + aMt0 + 4) * 64 + kt + 1) * 32) * 2 + aLi0];
            nb0 = g_WoF[((size_t)(ntBase + bNt0) * 64 + kt + 1) * 32 + bLi0];
            nb1 = g_WoF[((size_t)(ntBase + bNt0 + 8) * 64 + kt + 1) * 32 + bLi0];
        }

        uint4 a[2][2];
#pragma unroll
        for (int mtl = 0; mtl < 2; mtl++) {
            a[mtl][0] = As[p][wm * 2 + mtl][lane * 2];
            a[mtl][1] = As[p][wm * 2 + mtl][lane * 2 + 1];
        }
#pragma unroll
        for (int nt = 0; nt < 8; nt++) {
            uint4 bv = Bs[p][wn * 8 + nt][lane];
            uint32_t bh[2] = {bv.x, bv.y};
            uint32_t bl[2] = {bv.z, bv.w};
#pragma unroll
            for (int mtl = 0; mtl < 2; mtl++) {
                mma16816(acc[mtl][nt], (const uint32_t*)&a[mtl][0], bh);
                mma16816(acc[mtl][nt], (const uint32_t*)&a[mtl][0], bl);
                mma16816(acc[mtl][nt], (const uint32_t*)&a[mtl][1], bh);
            }
        }

        if (kt + 1 < 64) {
            const int q = p ^ 1;
            As[q][aMt0][aLi0] = na0;
            As[q][aMt0 + 4][aLi0] = na1;
            Bs[q][bNt0][bLi0] = nb0;
            Bs[q][bNt0 + 8][bLi0] = nb1;
        }
        __syncthreads();
    }
#undef STAGE

#pragma unroll
    for (int mtl = 0; mtl < 2; mtl++) {
        const int row0 = blockIdx.x * 128 + wm * 32 + mtl * 16 + (lane >> 2);
#pragma unroll
        for (int nt = 0; nt < 8; nt++) {
            const int col = blockIdx.y * 128 + wn * 64 + nt * 8 + (lane & 3) * 2;
            float2 bv = *(const float2*)(bias + col);
            float2 o0 = make_float2(acc[mtl][nt][0] + bv.x, acc[mtl][nt][1] + bv.y);
            float2 o1 = make_float2(acc[mtl][nt][2] + bv.x, acc[mtl][nt][3] + bv.y);
            *(float2*)(C + (size_t)row0 * 32000 + col) = o0;
            *(float2*)(C + (size_t)(row0 + 8) * 32000 + col) = o1;
        }
    }
}

// ---------------- Wo -> B-fragment conversion (runs once) ----------------
__global__ void __launch_bounds__(256) k_convWo(const float* __restrict__ Wo)
{
    int g = blockIdx.x * 256 + threadIdx.x;
    if (g >= 4000 * 64 * 32) return;
    int lane = g & 31;
    int kt = (g >> 5) & 63;
    int nt = g >> 11;
    int n = nt * 8 + (lane >> 2);
    int k0 = kt * 16 + (lane & 3) * 2;
    const float* p = Wo + (size_t)n * 1024 + k0;
    uint32_t h0, l0, h1, l1;
    split2(p[0], p[1], h0, l0);
    split2(p[8], p[9], h1, l1);
    g_WoF[g] = make_uint4(h0, h1, l0, l1);
}

// ---------------- recurrence weight fragment conversion (runs once) ----------------
__global__ void __launch_bounds__(256) k_convW(
    const float* __restrict__ Whh, const float* __restrict__ Wz,
    const float* __restrict__ Wh, const float* __restrict__ Wr)
{
    int g = blockIdx.x * 256 + threadIdx.x;
    if (g >= 28672 * 32) return;
    const int tile = g >> 5, lane = g & 31;
    const int rl = lane >> 2;
    const int kq = (lane & 3) * 2;
    const float *r0p, *r8p;
    uint4* dst;
    if (tile < 16384) {
        int rt = tile >> 6, kt = tile & 63;
        int j0 = (rt >> 1) * 8;
        int gate_lo = (rt & 1) * 2;
        int k0 = kt * 16 + kq;
        r0p = Whh + (size_t)(gate_lo * 1024 + j0 + rl) * 1024 + k0;
        r8p = Whh + (size_t)((gate_lo + 1) * 1024 + j0 + rl) * 1024 + k0;
        dst = g_WhhF + ((size_t)tile * 32 + lane) * 2;
    } else if (tile < 26624) {
        int t2 = tile - 16384;
        int rt = t2 >> 6, kt = t2 & 63;
        int k0 = kt * 16 + kq;
        const float* base;
        int row;
        if (rt < 64)      { base = Wz; row = rt * 16; }
        else if (rt < 128){ base = Wh; row = (rt - 64) * 16; }
        else              { base = Wr; row = (rt - 128) * 16; }
        r0p = base + (size_t)(row + rl) * 1536 + 512 + k0;
        r8p = base + (size_t)(row + rl + 8) * 1536 + 512 + k0;
        dst = g_WzrF + ((size_t)t2 * 32 + lane) * 2;
    } else {
        int t3 = tile - 26624;
        int rt = t3 >> 5, kt = t3 & 31;
        int k0 = kt * 16 + kq;
        r0p = Wh + (size_t)(rt * 16 + rl) * 1536 + k0;
        r8p = Wh + (size_t)(rt * 16 + rl + 8) * 1536 + k0;
        dst = g_WheF + ((size_t)t3 * 32 + lane) * 2;
    }
    uint4 hi, lo;
    split2(r0p[0], r0p[1], hi.x, lo.x);
    split2(r8p[0], r8p[1], hi.y, lo.y);
    split2(r0p[8], r0p[9], hi.z, lo.z);
    split2(r8p[8], r8p[9], hi.w, lo.w);
    dst[0] = hi;
    dst[1] = lo;
}

// ---------------- shared step-MMA slice (no smem operands) ----------------
__device__ __forceinline__ void step_mma_slice(
    const uint4* __restrict__ Af, const uint4* __restrict__ Bf,
    int rt, int ktTot, int kt0, int ktN, int lane, float acc[4][4])
{
#pragma unroll 2
    for (int kt = kt0; kt < kt0 + ktN; kt++) {
        const uint4* ap = Af + (((size_t)rt * ktTot + kt) * 32 + lane) * 2;
        uint4 ahi = ap[0];
        uint4 alo = ap[1];
        const uint4* bp = Bf + (size_t)(kt * 4) * 32 + lane;
        uint4 bv0 = bp[0], bv1 = bp[32], bv2 = bp[64], bv3 = bp[96];
        uint4 bvs[4] = {bv0, bv1, bv2, bv3};
#pragma unroll
        for (int nt = 0; nt < 4; nt++) {
            uint32_t bh2[2] = {bvs[nt].x, bvs[nt].y};
            uint32_t bl2[2] = {bvs[nt].z, bvs[nt].w};
            mma16816(acc[nt], (const uint32_t*)&ahi, bh2);
            mma16816(acc[nt], (const uint32_t*)&ahi, bl2);
            mma16816(acc[nt], (const uint32_t*)&alo, bh2);
        }
    }
}

__device__ __forceinline__ void store_cfrag(float S[8][16][33], int wid, int lane,
                                            float acc[4][4])
{
    int r = lane >> 2, c0 = (lane & 3) * 2;
#pragma unroll
    for (int nt = 0; nt < 4; nt++) {
        S[wid][r][nt * 8 + c0]     = acc[nt][0];
        S[wid][r][nt * 8 + c0 + 1] = acc[nt][1];
        S[wid][r + 8][nt * 8 + c0]     = acc[nt][2];
        S[wid][r + 8][nt * 8 + c0 + 1] = acc[nt][3];
    }
}

// ---------------- step 1: gates MMA + LSTM pointwise ----------------
__global__ void __launch_bounds__(256) gates_mma(int t)
{
    __shared__ float S[8][16][33];
    const int tid = threadIdx.x, lane = tid & 31, wid = tid >> 5;
    const int bid = blockIdx.x;
    const int mt = wid & 1, ks = wid >> 1;
    float acc[4][4] = {};
    step_mma_slice(g_WhhF, g_hF, bid * 2 + mt, 64, ks * 16, 16, lane, acc);
    store_cfrag(S, wid, lane, acc);
    __syncthreads();

    const int jl = tid >> 5, b = tid & 31;
    const int j = bid * 8 + jl;
    float gi = 0, gf = 0, gg = 0, go = 0;
#pragma unroll
    for (int k = 0; k < 4; k++) {
        gi += S[k * 2][jl][b];     gf += S[k * 2][jl + 8][b];
        gg += S[k * 2 + 1][jl][b]; go += S[k * 2 + 1][jl + 8][b];
    }
    const float* gx = g_gx + (size_t)(t * 32 + b) * 4096 + j;
    gi += gx[0]; gf += gx[1024]; gg += gx[2048]; go += gx[3072];
    float c = g_cT[j * 32 + b];
    float cn = sigf(gf) * c + sigf(gi) * tanhf(gg);
    g_cT[j * 32 + b] = cn;
    float h1 = sigf(go) * tanhf(cn);
    g_h1T[j * 32 + b] = h1;
    __syncthreads();
    S[0][jl][b] = h1;
    __syncthreads();
    if (tid < 128) {
        int nt = tid >> 5, l = tid & 31;
        int k0l = (l & 3) * 2, n = nt * 8 + (l >> 2);
        uint32_t hh_, ll_;
        split2(S[0][k0l][n], S[0][k0l + 1][n], hh_, ll_);
        int kt = bid >> 1, half = bid & 1;
        uint32_t* d = (uint32_t*)&g_h1F[(kt * 4 + nt) * 32 + l];
        d[half] = hh_;
        d[2 + half] = ll_;
    }
}

// ---------------- step 2: z / t1 / r*we MMA ----------------
__global__ void __launch_bounds__(256) zrt_mma()
{
    __shared__ float S[8][16][33];
    const int tid = threadIdx.x, lane = tid & 31, wid = tid >> 5;
    const int bid = blockIdx.x;
    const int mt = wid & 1, ks = wid >> 1;
    float acc[4][4] = {};
    step_mma_slice(g_WzrF, g_h1F, bid * 2 + mt, 64, ks * 16, 16, lane, acc);
    store_cfrag(S, wid, lane, acc);
    __syncthreads();

    const int m = tid >> 3, nq = (tid & 7) * 4;
    float v[4];
#pragma unroll
    for (int q = 0; q < 4; q++) {
        float s = 0;
#pragma unroll
        for (int k = 0; k < 4; k++) s += S[(k << 1) | (m >> 4)][m & 15][nq + q];
        v[q] = s;
    }
    if (bid < 32) {
        int j = bid * 32 + m;
#pragma unroll
        for (int q = 0; q < 4; q++)
            g_zT[j * 32 + nq + q] = sigf(g_zcT[j * 32 + nq + q] + v[q]);
    } else if (bid < 64) {
        int j = (bid - 32) * 32 + m;
#pragma unroll
        for (int q = 0; q < 4; q++) g_t1T[j * 32 + nq + q] = v[q];
    } else {
        int e = (bid - 64) * 32 + m;
        float rw[4];
#pragma unroll
        for (int q = 0; q < 4; q++)
            rw[q] = sigf(g_rcT[e * 32 + nq + q] + v[q]) * g_weT[e * 32 + nq + q];
        __syncthreads();
        float (*S2)[33] = (float(*)[33])S;
#pragma unroll
        for (int q = 0; q < 4; q++) S2[m][nq + q] = rw[q];
        __syncthreads();
        int ktl = tid >> 7, nt = (tid >> 5) & 3, l = tid & 31;
        int k0l = ktl * 16 + (l & 3) * 2, n = nt * 8 + (l >> 2);
        uint32_t h0, l0, h1, l1;
        split2(S2[k0l][n],     S2[k0l + 1][n], h0, l0);
        split2(S2[k0l + 8][n], S2[k0l + 9][n], h1, l1);
        int kt = (bid - 64) * 2 + ktl;
        g_rwF[(kt * 4 + nt) * 32 + l] = make_uint4(h0, h1, l0, l1);
    }
}

// ---------------- step 3: hh MMA + h update + hF/hsF frag writes ----------------
__global__ void __launch_bounds__(256) hh_mma(const float* __restrict__ bh, int t)
{
    __shared__ float S[8][16][33];
    const int tid = threadIdx.x, lane = tid & 31, wid = tid >> 5;
    const int bid = blockIdx.x;
    const int mt = wid & 1, ks = wid >> 1;
    float acc[4][4] = {};
    step_mma_slice(g_WheF, g_rwF, bid * 2 + mt, 32, ks * 8, 8, lane, acc);
    store_cfrag(S, wid, lane, acc);
    __syncthreads();

    const int m = tid >> 3, nq = (tid & 7) * 4;
    float v[4];
#pragma unroll
    for (int q = 0; q < 4; q++) {
        float s = 0;
#pragma unroll
        for (int k = 0; k < 4; k++) s += S[(k << 1) | (m >> 4)][m & 15][nq + q];
        v[q] = s;
    }
    const int j = bid * 32 + m;
    const float bhv = bh[j];
    float hn[4];
#pragma unroll
    for (int q = 0; q < 4; q++) {
        int b = nq + q;
        float hh = tanhf(g_t1T[j * 32 + b] + v[q] + bhv);
        float z = g_zT[j * 32 + b];
        float h1 = g_h1T[j * 32 + b];
        hn[q] = (1.f - z) * h1 + z * hh;
        g_hT[j * 32 + b] = hn[q];
    }
    __syncthreads();
    float (*S2)[33] = (float(*)[33])S;    // S2[j_local][b]
#pragma unroll
    for (int q = 0; q < 4; q++) S2[m][nq + q] = hn[q];
    __syncthreads();
    {   // B-frag write for next-step h (g_hF)
        int ktl = tid >> 7, nt = (tid >> 5) & 3, l = tid & 31;
        int k0l = ktl * 16 + (l & 3) * 2, n = nt * 8 + (l >> 2);
        uint32_t h0, l0, h1, l1;
        split2(S2[k0l][n],     S2[k0l + 1][n], h0, l0);
        split2(S2[k0l + 8][n], S2[k0l + 9][n], h1, l1);
        int kt = bid * 2 + ktl;
        g_hF[(kt * 4 + nt) * 32 + l] = make_uint4(h0, h1, l0, l1);
    }
    if (tid < 128) {   // A-frag write for logits GEMM (g_hsF)
        int sub = tid >> 5, l = tid & 31;
        int mtl = sub & 1, ktl = sub >> 1;
        int r = l >> 2, kq = (l & 3) * 2;
        int k0 = ktl * 16 + kq, br = mtl * 16 + r;
        uint4 hi, lo;
        split2(S2[k0][br],      S2[k0 + 1][br],      hi.x, lo.x);
        split2(S2[k0][br + 8],  S2[k0 + 1][br + 8],  hi.y, lo.y);
        split2(S2[k0 + 8][br],  S2[k0 + 9][br],      hi.z, lo.z);
        split2(S2[k0 + 8][br + 8], S2[k0 + 9][br + 8], hi.w, lo.w);
        int mtg = 2 * t + mtl, ktg = bid * 2 + ktl;
        uint4* d = g_hsF + ((size_t)(mtg * 64 + ktg) * 32 + l) * 2;
        d[0] = hi;
        d[1] = lo;
    }
}

// ---------------- gather: we (transposed), se, bias sum ----------------
__global__ void k_gather(const int* __restrict__ word, const int* __restrict__ seq,
                         const float* __restrict__ emb,
                         const float* __restrict__ bih, const float* __restrict__ bhh)
{
    int idx = blockIdx.x * blockDim.x + threadIdx.x;
    if (idx < 1024 * 512) {
        int m = idx >> 9, e = idx & 511;
        g_se[idx] = emb[(size_t)seq[m] * 512 + e];
    }
    if (idx < 512 * 32) {
        int e = idx >> 5, b = idx & 31;
        g_weT[idx] = emb[(size_t)word[b] * 512 + e];
    }
    if (idx < 4096) g_bsum[idx] = bih[idx] + bhh[idx];
}

// ================= fp32 micro-GEMM core (prep only) =================
template<int T>
__device__ __forceinline__ void gemm_core(
    float (*As)[16][64], float (*Bs)[16][32], float (*Red)[32][32],
    const float* arow, const float* brow, int kg, int s)
{
    const int r = s >> 1, kofs = (s & 1) * 8;
    const int bk = s >> 2, bofs = (s & 3) * 8;
    const int mthr = s >> 3, nthr = s & 7;
    const int m0 = mthr * 4, n0 = nthr * 4;

    u64 acc[4][2];
#pragma unroll
    for (int i = 0; i < 4; i++) { acc[i][0] = 0ull; acc[i][1] = 0ull; }

    const float* aP = arow + kofs;
    const float* bP = brow + bk * 32 + bofs;

    float4 a0 = *(const float4*)aP;
    float4 a1 = *(const float4*)(aP + 4);
    float4 b0 = *(const float4*)bP;
    float4 b1 = *(const float4*)(bP + 4);

#pragma unroll 1
    for (int t = 0; t < T; t++) {
        {
            float va[8] = {a0.x, a0.y, a0.z, a0.w, a1.x, a1.y, a1.z, a1.w};
#pragma unroll
            for (int i = 0; i < 8; i++) {
                float2 d = make_float2(va[i], va[i]);
                *(float2*)&As[kg][kofs + i][2 * r] = d;
            }
            *(float4*)&Bs[kg][bk][bofs]     = b0;
            *(float4*)&Bs[kg][bk][bofs + 4] = b1;
        }
        __syncthreads();
        if (t + 1 < T) {
            aP += 16; bP += 512;
            a0 = *(const float4*)aP;
            a1 = *(const float4*)(aP + 4);
            b0 = *(const float4*)bP;
            b1 = *(const float4*)(bP + 4);
        }
#pragma unroll
        for (int k = 0; k < 16; k++) {
            float4 av0 = *(const float4*)&As[kg][k][2 * m0];
            float4 av1 = *(const float4*)&As[kg][k][2 * m0 + 4];
            float4 bv  = *(const float4*)&Bs[kg][k][n0];
            const u64* ap0 = (const u64*)&av0;
            const u64* ap1 = (const u64*)&av1;
            const u64* bp  = (const u64*)&bv;
            acc[0][0] = fma2(ap0[0], bp[0], acc[0][0]);
            acc[0][1] = fma2(ap0[0], bp[1], acc[0][1]);
            acc[1][0] = fma2(ap0[1], bp[0], acc[1][0]);
            acc[1][1] = fma2(ap0[1], bp[1], acc[1][1]);
            acc[2][0] = fma2(ap1[0], bp[0], acc[2][0]);
            acc[2][1] = fma2(ap1[0], bp[1], acc[2][1]);
            acc[3][0] = fma2(ap1[1], bp[0], acc[3][0]);
            acc[3][1] = fma2(ap1[1], bp[1], acc[3][1]);
        }
        __syncthreads();
    }
#pragma unroll
    for (int i = 0; i < 4; i++) {
        *(float2*)&Red[kg][m0 + i][n0]     = *(float2*)&acc[i][0];
        *(float2*)&Red[kg][m0 + i][n0 + 2] = *(float2*)&acc[i][1];
    }
    __syncthreads();
}

// ---------------- prep: h0 (-> h,c,hF), zc, rc ----------------
__global__ void __launch_bounds__(256) k_prep2(
    const float* __restrict__ Wl, const float* __restrict__ bl,
    const float* __restrict__ Wz, const float* __restrict__ bz,
    const float* __restrict__ Wr, const float* __restrict__ br)
{
    __shared__ __align__(16) float As[4][16][64];
    __shared__ __align__(16) float Bs[4][16][32];
    __shared__ float Red[4][32][32];
    const int tid = threadIdx.x;
    const int kg = tid >> 6, s = tid & 63;
    const int mbase = blockIdx.x * 32;
    const int w = mbase + (s >> 1);
    const float* arow;
    if (w < 1024)      arow = Wl + (size_t)w * 512;
    else if (w < 2048) arow = Wz + (size_t)(w - 1024) * 1536;
    else               arow = Wr + (size_t)(w - 2048) * 1536;
    arow += kg * 128;
    const float* brow = g_weT + kg * 128 * 32;
    gemm_core<8>(As, Bs, Red, arow, brow, kg, s);

    const int m = tid >> 3, nq = (tid & 7) * 4;
    const int wo = mbase + m;
    float4 v0 = *(float4*)&Red[0][m][nq];
    float4 v1 = *(float4*)&Red[1][m][nq];
    float4 v2 = *(float4*)&Red[2][m][nq];
    float4 v3 = *(float4*)&Red[3][m][nq];
    float v[4] = { v0.x + v1.x + v2.x + v3.x, v0.y + v1.y + v2.y + v3.y,
                   v0.z + v1.z + v2.z + v3.z, v0.w + v1.w + v2.w + v3.w };
    if (wo < 1024) {
        float bb = bl[wo];
        float h0v[4];
#pragma unroll
        for (int q = 0; q < 4; q++) {
            h0v[q] = v[q] + bb;
            g_hT[wo * 32 + nq + q] = h0v[q];
            g_cT[wo * 32 + nq + q] = h0v[q];
        }
        __syncthreads();
        float (*S2)[33] = (float(*)[33])&As[0][0][0];
#pragma unroll
        for (int q = 0; q < 4; q++) S2[m][nq + q] = h0v[q];
        __syncthreads();
        int ktl = tid >> 7, nt = (tid >> 5) & 3, l = tid & 31;
        int k0l = ktl * 16 + (l & 3) * 2, n = nt * 8 + (l >> 2);
        uint32_t h0, l0, h1, l1;
        split2(S2[k0l][n],     S2[k0l + 1][n], h0, l0);
        split2(S2[k0l + 8][n], S2[k0l + 9][n], h1, l1);
        int kt = blockIdx.x * 2 + ktl;
        g_hF[(kt * 4 + nt) * 32 + l] = make_uint4(h0, h1, l0, l1);
    } else if (wo < 2048) {
        int i = wo - 1024; float bb = bz[i];
#pragma unroll
        for (int q = 0; q < 4; q++) g_zcT[i * 32 + nq + q] = v[q] + bb;
    } else {
        int e = wo - 2048; float bb = br[e];
#pragma unroll
        for (int q = 0; q < 4; q++) g_rcT[e * 32 + nq + q] = v[q] + bb;
    }
}

// ---------------- tail: hf, cf into output ----------------
__global__ void k_tail(float* __restrict__ out)
{
    int idx = blockIdx.x * blockDim.x + threadIdx.x;   // < 32768
    int b = idx >> 10, j = idx & 1023;
    out[32768000 + idx]         = g_hT[j * 32 + b];
    out[32768000 + 32768 + idx] = g_cT[j * 32 + b];
}

// ---------------- launch ----------------
extern "C" void kernel_launch(void* const* d_in, const int* in_sizes, int n_in,
                              void* d_out, int out_size)
{
    const int*   word = (const int*)d_in[0];
    const int*   seq  = (const int*)d_in[1];
    const float* emb  = (const float*)d_in[2];
    const float* Wl   = (const float*)d_in[3];
    const float* bl   = (const float*)d_in[4];
    const float* Wih  = (const float*)d_in[5];
    const float* Whh  = (const float*)d_in[6];
    const float* bih  = (const float*)d_in[7];
    const float* bhh  = (const float*)d_in[8];
    const float* Wz   = (const float*)d_in[9];
    const float* bz   = (const float*)d_in[10];
    const float* Wr   = (const float*)d_in[11];
    const float* br   = (const float*)d_in[12];
    const float* Wh   = (const float*)d_in[13];
    const float* bh   = (const float*)d_in[14];
    const float* Wo   = (const float*)d_in[15];
    const float* bo   = (const float*)d_in[16];
    float* out = (float*)d_out;

    void *p_se, *p_gx, *p_bsum;
    cudaGetSymbolAddress(&p_se, g_se);
    cudaGetSymbolAddress(&p_gx, g_gx);
    cudaGetSymbolAddress(&p_bsum, g_bsum);

    cudaFuncSetAttribute(gemm_mma, cudaFuncAttributeMaxDynamicSharedMemorySize, GM_SMEM);

    k_convW<<<3584, 256>>>(Whh, Wz, Wh, Wr);
    k_convWo<<<32000, 256>>>(Wo);
    k_gather<<<2048, 256>>>(word, seq, emb, bih, bhh);
    k_prep2<<<80, 256>>>(Wl, bl, Wz, bz, Wr, br);

    // gx = se @ Wih.T + (bih+bhh):  M=1024, N=4096, K=512  (HMMA split-bf16)
    gemm_mma<<<dim3(8, 32), 256, GM_SMEM>>>((const float*)p_se, Wih,
                                            (const float*)p_bsum, (float*)p_gx,
                                            512, 4096);

    for (int t = 0; t < 32; t++) {
        gates_mma<<<128, 256>>>(t);
        zrt_mma<<<80, 256>>>();
        hh_mma<<<32, 256>>>(bh, t);
    }

    // logits = hsF @ WoF^T + bo  (fragment-fed HMMA, smem-dedup staging)
    gemm_logits<<<dim3(8, 250), 256>>>(bo, out);

    k_tail<<<128, 256>>>(out);
}